// round 1
// baseline (speedup 1.0000x reference)
#include <cuda_runtime.h>

// Problem constants (fixed by setup_inputs)
#define Bb 4
#define Tt 2048
#define Cc 768
#define Hh 12
#define DH 64
#define Mm (Bb * Tt)      // 8192
#define N3 (3 * Cc)       // 2304

// Scratch: q/k/v in [B, H, T, Dh] layout. ~25.2 MB each (device globals — allowed).
__device__ float g_q[(size_t)Bb * Hh * Tt * DH];
__device__ float g_k[(size_t)Bb * Hh * Tt * DH];
__device__ float g_v[(size_t)Bb * Hh * Tt * DH];

// ---------------------------------------------------------------------------
// Kernel 1: qkv = x @ W + b, scattered into g_q / g_k / g_v ([B,H,T,Dh]).
// 128x128 block tile, BK=16, 256 threads, 8x8 per-thread microtile.
// ---------------------------------------------------------------------------
__global__ __launch_bounds__(256, 2)
void qkv_gemm(const float* __restrict__ A,      // x  [M, 768]
              const float* __restrict__ W,      // W  [768, 2304]
              const float* __restrict__ bias)   // b  [2304]
{
    __shared__ float As[16][128];   // A^T tile: As[k][m]
    __shared__ float Bs[16][128];   // B tile:   Bs[k][n]

    const int tid = threadIdx.x;
    const int m0 = blockIdx.y * 128;
    const int n0 = blockIdx.x * 128;
    const int tm = tid >> 4;        // 0..15
    const int tn = tid & 15;        // 0..15

    float acc[8][8];
#pragma unroll
    for (int i = 0; i < 8; i++)
#pragma unroll
        for (int j = 0; j < 8; j++) acc[i][j] = 0.f;

    for (int k0 = 0; k0 < Cc; k0 += 16) {
#pragma unroll
        for (int l = 0; l < 2; l++) {
            int f = tid + l * 256;                 // 0..511
            // A tile: 128 rows x 16 cols = 512 float4 (4 per row)
            int r  = f >> 2;
            int cv = (f & 3) << 2;
            float4 a = *(const float4*)&A[(size_t)(m0 + r) * Cc + k0 + cv];
            As[cv + 0][r] = a.x;
            As[cv + 1][r] = a.y;
            As[cv + 2][r] = a.z;
            As[cv + 3][r] = a.w;
            // B tile: 16 rows x 128 cols = 512 float4 (32 per row)
            int r2  = f >> 5;
            int cv2 = (f & 31) << 2;
            *(float4*)&Bs[r2][cv2] =
                *(const float4*)&W[(size_t)(k0 + r2) * N3 + n0 + cv2];
        }
        __syncthreads();

#pragma unroll
        for (int kk = 0; kk < 16; kk++) {
            float a[8], b[8];
#pragma unroll
            for (int i = 0; i < 8; i++) a[i] = As[kk][tm * 8 + i];
#pragma unroll
            for (int j = 0; j < 8; j++) b[j] = Bs[kk][tn * 8 + j];
#pragma unroll
            for (int i = 0; i < 8; i++)
#pragma unroll
                for (int j = 0; j < 8; j++)
                    acc[i][j] += a[i] * b[j];
        }
        __syncthreads();
    }

    // Epilogue: add bias and scatter. Since 128 | 768, a block's n-range lies
    // entirely within one of {q, k, v}.
    const int which = n0 / Cc;
    float* dst = (which == 0) ? g_q : (which == 1) ? g_k : g_v;
    const int nb = n0 - which * Cc;

#pragma unroll
    for (int i = 0; i < 8; i++) {
        int m  = m0 + tm * 8 + i;
        int b_ = m >> 11;           // / 2048
        int t  = m & (Tt - 1);
#pragma unroll
        for (int j = 0; j < 8; j++) {
            int n = nb + tn * 8 + j;
            int h = n >> 6;
            int d = n & 63;
            dst[(((size_t)b_ * Hh + h) * Tt + t) * DH + d] =
                acc[i][j] + bias[which * Cc + n];
        }
    }
}

// ---------------------------------------------------------------------------
// Kernel 2: streaming causal ReLU attention.
// Block = (qt, h, b). BQ=BK=64, Dh=64, 256 threads (16x16), 4x4 microtiles.
// Smem: Qt[d][i] (scale-folded), KP[..] (K^T then reused for P), Vs[j][d].
// Exactly 48 KB static smem -> 4 blocks/SM.
// ---------------------------------------------------------------------------
__global__ __launch_bounds__(256)
void attn_kernel(float* __restrict__ out)
{
    __shared__ float Qt[DH][64];    // Qt[d][i], i = q row in tile
    __shared__ float KP[64][64];    // phase 1: Kt[d][j]; phase 2: Ps[i][j]
    __shared__ float Vs[64][DH];    // Vs[j][d]

    const int qt  = blockIdx.x;
    const int h   = blockIdx.y;
    const int b   = blockIdx.z;
    const int tid = threadIdx.x;
    const int ty  = tid >> 4;       // 0..15 (q rows)
    const int tx  = tid & 15;       // 0..15 (k cols / d cols)

    const size_t base = ((size_t)b * Hh + h) * Tt * DH;
    const float* Qh = g_q + base;
    const float* Kh = g_k + base;
    const float* Vh = g_v + base;

    float o[4][4];
#pragma unroll
    for (int i = 0; i < 4; i++)
#pragma unroll
        for (int j = 0; j < 4; j++) o[i][j] = 0.f;

    // Load Q tile once, transposed + scaled by 1/sqrt(64) = 0.125.
#pragma unroll
    for (int l = 0; l < 4; l++) {
        int f  = tid + l * 256;       // 0..1023 (64 rows x 16 float4)
        int r  = f >> 4;
        int cv = (f & 15) << 2;
        float4 q4 = *(const float4*)&Qh[(size_t)(qt * 64 + r) * DH + cv];
        Qt[cv + 0][r] = q4.x * 0.125f;
        Qt[cv + 1][r] = q4.y * 0.125f;
        Qt[cv + 2][r] = q4.z * 0.125f;
        Qt[cv + 3][r] = q4.w * 0.125f;
    }

    for (int kt = 0; kt <= qt; kt++) {
        __syncthreads();   // prior iter done with KP (as P) and Vs; also fences Qt on iter 0 path

        // Load K tile (transposed into KP) and V tile (natural) for this kt.
#pragma unroll
        for (int l = 0; l < 4; l++) {
            int f  = tid + l * 256;
            int r  = f >> 4;
            int cv = (f & 15) << 2;
            float4 k4 = *(const float4*)&Kh[(size_t)(kt * 64 + r) * DH + cv];
            KP[cv + 0][r] = k4.x;
            KP[cv + 1][r] = k4.y;
            KP[cv + 2][r] = k4.z;
            KP[cv + 3][r] = k4.w;
            *(float4*)&Vs[r][cv] =
                *(const float4*)&Vh[(size_t)(kt * 64 + r) * DH + cv];
        }
        __syncthreads();

        // S = (Q*scale) . K^T  for this 64x64 tile, 4x4 per thread.
        float s[4][4];
#pragma unroll
        for (int i = 0; i < 4; i++)
#pragma unroll
            for (int j = 0; j < 4; j++) s[i][j] = 0.f;

#pragma unroll 8
        for (int d = 0; d < DH; d++) {
            float a[4], bb[4];
#pragma unroll
            for (int ii = 0; ii < 4; ii++) a[ii]  = Qt[d][ty * 4 + ii];
#pragma unroll
            for (int jj = 0; jj < 4; jj++) bb[jj] = KP[d][tx * 4 + jj];
#pragma unroll
            for (int ii = 0; ii < 4; ii++)
#pragma unroll
                for (int jj = 0; jj < 4; jj++)
                    s[ii][jj] += a[ii] * bb[jj];
        }
        __syncthreads();   // everyone done reading KP as K^T

        // Mask (causal) + ReLU, store P into KP (reused buffer), layout P[i][j].
        const bool diag = (kt == qt);
#pragma unroll
        for (int ii = 0; ii < 4; ii++) {
            int qi = ty * 4 + ii;
            float v0 = fmaxf(s[ii][0], 0.f);
            float v1 = fmaxf(s[ii][1], 0.f);
            float v2 = fmaxf(s[ii][2], 0.f);
            float v3 = fmaxf(s[ii][3], 0.f);
            if (diag) {
                if (tx * 4 + 0 > qi) v0 = 0.f;
                if (tx * 4 + 1 > qi) v1 = 0.f;
                if (tx * 4 + 2 > qi) v2 = 0.f;
                if (tx * 4 + 3 > qi) v3 = 0.f;
            }
            *(float4*)&KP[qi][tx * 4] = make_float4(v0, v1, v2, v3);
        }
        __syncthreads();

        // O += P . V   (thread owns O rows ty*4+ii, cols d = tx*4+dd)
#pragma unroll 8
        for (int j = 0; j < 64; j++) {
            float bb[4];
#pragma unroll
            for (int dd = 0; dd < 4; dd++) bb[dd] = Vs[j][tx * 4 + dd];
#pragma unroll
            for (int ii = 0; ii < 4; ii++) {
                float a = KP[ty * 4 + ii][j];
#pragma unroll
                for (int dd = 0; dd < 4; dd++)
                    o[ii][dd] += a * bb[dd];
            }
        }
    }

    // Write O to out[b][t][h*64 + d], t = qt*64 + ty*4 + ii, d = tx*4 + dd.
    float* op = out + ((size_t)b * Tt + (size_t)qt * 64 + ty * 4) * Cc + h * DH + tx * 4;
#pragma unroll
    for (int ii = 0; ii < 4; ii++) {
        *(float4*)&op[(size_t)ii * Cc] = make_float4(o[ii][0], o[ii][1], o[ii][2], o[ii][3]);
    }
}

// ---------------------------------------------------------------------------
extern "C" void kernel_launch(void* const* d_in, const int* in_sizes, int n_in,
                              void* d_out, int out_size)
{
    const float* x    = (const float*)d_in[0];
    const float* W    = (const float*)d_in[1];
    const float* bias = (const float*)d_in[2];
    float* out        = (float*)d_out;
    (void)in_sizes; (void)n_in; (void)out_size;

    dim3 g1(N3 / 128, Mm / 128);    // (18, 64)
    qkv_gemm<<<g1, 256>>>(x, W, bias);

    dim3 g2(Tt / 64, Hh, Bb);       // (32, 12, 4)
    attn_kernel<<<g2, 256>>>(out);
}

// round 2
// speedup vs baseline: 1.1796x; 1.1796x over previous
#include <cuda_runtime.h>

// Problem constants (fixed by setup_inputs)
#define Bb 4
#define Tt 2048
#define Cc 768
#define Hh 12
#define DH 64
#define Mm (Bb * Tt)      // 8192
#define N3 (3 * Cc)       // 2304

// Scratch. Q and K are stored TRANSPOSED per head: [B, H, Dh, T].
// V is natural: [B, H, T, Dh]. Q has the 1/sqrt(Dh) scale folded in.
__device__ float g_q[(size_t)Bb * Hh * Tt * DH];
__device__ float g_k[(size_t)Bb * Hh * Tt * DH];
__device__ float g_v[(size_t)Bb * Hh * Tt * DH];

// ---------------------------------------------------------------------------
// Kernel 1: qkv = x @ W + b. Double-buffered 128x128x16 SGEMM, 256 threads,
// 8x8 microtiles. Epilogue scatters Q,K transposed ([B,H,D,T], Q scaled) and
// V natural ([B,H,T,D]).
// ---------------------------------------------------------------------------
__global__ __launch_bounds__(256, 2)
void qkv_gemm(const float* __restrict__ A,      // x  [M, 768]
              const float* __restrict__ W,      // W  [768, 2304]
              const float* __restrict__ bias)   // b  [2304]
{
    __shared__ float As[2][16][128];   // A^T tile: As[buf][k][m]
    __shared__ float Bs[2][16][128];   // B tile:   Bs[buf][k][n]

    const int tid = threadIdx.x;
    const int m0 = blockIdx.y * 128;
    const int n0 = blockIdx.x * 128;
    const int tm = tid >> 4;        // 0..15
    const int tn = tid & 15;        // 0..15

    // Per-thread global-load coordinates (2 float4 each for A and B)
    const int arow0 = tid >> 2;            // 0..63   (A rows, +64 for l=1)
    const int acol  = (tid & 3) << 2;      // 0,4,8,12
    const int brow0 = tid >> 5;            // 0..7    (B rows, +8 for l=1)
    const int bcol  = (tid & 31) << 2;     // 0..124

    float acc[8][8];
#pragma unroll
    for (int i = 0; i < 8; i++)
#pragma unroll
        for (int j = 0; j < 8; j++) acc[i][j] = 0.f;

    float4 pa0, pa1, pb0, pb1;

    // Prologue: load k-tile 0 into buffer 0
    pa0 = *(const float4*)&A[(size_t)(m0 + arow0) * Cc + acol];
    pa1 = *(const float4*)&A[(size_t)(m0 + arow0 + 64) * Cc + acol];
    pb0 = *(const float4*)&W[(size_t)brow0 * N3 + n0 + bcol];
    pb1 = *(const float4*)&W[(size_t)(brow0 + 8) * N3 + n0 + bcol];
    As[0][acol + 0][arow0] = pa0.x;  As[0][acol + 1][arow0] = pa0.y;
    As[0][acol + 2][arow0] = pa0.z;  As[0][acol + 3][arow0] = pa0.w;
    As[0][acol + 0][arow0 + 64] = pa1.x;  As[0][acol + 1][arow0 + 64] = pa1.y;
    As[0][acol + 2][arow0 + 64] = pa1.z;  As[0][acol + 3][arow0 + 64] = pa1.w;
    *(float4*)&Bs[0][brow0][bcol]     = pb0;
    *(float4*)&Bs[0][brow0 + 8][bcol] = pb1;
    __syncthreads();

    int cur = 0;
    for (int k0 = 0; k0 < Cc; k0 += 16) {
        const int nk = k0 + 16;
        if (nk < Cc) {
            pa0 = *(const float4*)&A[(size_t)(m0 + arow0) * Cc + nk + acol];
            pa1 = *(const float4*)&A[(size_t)(m0 + arow0 + 64) * Cc + nk + acol];
            pb0 = *(const float4*)&W[(size_t)(nk + brow0) * N3 + n0 + bcol];
            pb1 = *(const float4*)&W[(size_t)(nk + brow0 + 8) * N3 + n0 + bcol];
        }

#pragma unroll
        for (int kk = 0; kk < 16; kk++) {
            float a[8], b[8];
            *(float4*)&a[0] = *(const float4*)&As[cur][kk][tm * 8];
            *(float4*)&a[4] = *(const float4*)&As[cur][kk][tm * 8 + 4];
            *(float4*)&b[0] = *(const float4*)&Bs[cur][kk][tn * 8];
            *(float4*)&b[4] = *(const float4*)&Bs[cur][kk][tn * 8 + 4];
#pragma unroll
            for (int i = 0; i < 8; i++)
#pragma unroll
                for (int j = 0; j < 8; j++)
                    acc[i][j] += a[i] * b[j];
        }

        if (nk < Cc) {
            const int nxt = cur ^ 1;
            As[nxt][acol + 0][arow0] = pa0.x;  As[nxt][acol + 1][arow0] = pa0.y;
            As[nxt][acol + 2][arow0] = pa0.z;  As[nxt][acol + 3][arow0] = pa0.w;
            As[nxt][acol + 0][arow0 + 64] = pa1.x;  As[nxt][acol + 1][arow0 + 64] = pa1.y;
            As[nxt][acol + 2][arow0 + 64] = pa1.z;  As[nxt][acol + 3][arow0 + 64] = pa1.w;
            *(float4*)&Bs[nxt][brow0][bcol]     = pb0;
            *(float4*)&Bs[nxt][brow0 + 8][bcol] = pb1;
        }
        __syncthreads();
        cur ^= 1;
    }

    // ---- Epilogue ----
    const int which = n0 / Cc;                 // 0=Q, 1=K, 2=V (128 | 768)
    const int nb = n0 - which * Cc;
    const int m_lo = m0 + tm * 8;              // 8 consecutive m's
    const int b_  = m_lo >> 11;                // block never crosses batch
    const int t0  = m_lo & (Tt - 1);

    if (which < 2) {
        // Transposed store: dst[((b*H + h)*Dh + d) * T + t], t contiguous.
        float* dst = (which == 0) ? g_q : g_k;
        const float scale = (which == 0) ? 0.125f : 1.0f;
#pragma unroll
        for (int j = 0; j < 8; j++) {
            const int n = nb + tn * 8 + j;
            const int hh = n >> 6;
            const int d  = n & 63;
            const float bv = bias[which * Cc + n];
            float* p = dst + (((size_t)b_ * Hh + hh) * DH + d) * Tt + t0;
            float4 v0 = make_float4((acc[0][j] + bv) * scale, (acc[1][j] + bv) * scale,
                                    (acc[2][j] + bv) * scale, (acc[3][j] + bv) * scale);
            float4 v1 = make_float4((acc[4][j] + bv) * scale, (acc[5][j] + bv) * scale,
                                    (acc[6][j] + bv) * scale, (acc[7][j] + bv) * scale);
            *(float4*)p       = v0;
            *(float4*)(p + 4) = v1;
        }
    } else {
        // Natural store for V: g_v[((b*H + h)*T + t)*Dh + d], d contiguous.
        const int nlo = nb + tn * 8;
        const int hh  = nlo >> 6;              // 8-wide j-range stays in one head
        const int d0  = nlo & 63;
        const float* bp = bias + 2 * Cc + nlo;
        float bv[8];
#pragma unroll
        for (int j = 0; j < 8; j++) bv[j] = bp[j];
#pragma unroll
        for (int i = 0; i < 8; i++) {
            const int t = t0 + i;
            float* p = g_v + (((size_t)b_ * Hh + hh) * Tt + t) * DH + d0;
            float4 v0 = make_float4(acc[i][0] + bv[0], acc[i][1] + bv[1],
                                    acc[i][2] + bv[2], acc[i][3] + bv[3]);
            float4 v1 = make_float4(acc[i][4] + bv[4], acc[i][5] + bv[5],
                                    acc[i][6] + bv[6], acc[i][7] + bv[7]);
            *(float4*)p       = v0;
            *(float4*)(p + 4) = v1;
        }
    }
}

// ---------------------------------------------------------------------------
// Kernel 2: streaming causal ReLU attention.
// 64 threads/block, BQ=BK=64, 8x8 microtile in BOTH gemms (1 B/FMA).
// Smem: Qt[d][i] | KP (K^T[d][j] then P[i][j]) | Vs[j][d]  = 48KB exactly.
// Q,K read from transposed [B,H,D,T] scratch -> no in-kernel transpose.
// ---------------------------------------------------------------------------
__global__ __launch_bounds__(64)
void attn_kernel(float* __restrict__ out)
{
    __shared__ float Qt[DH][64];    // Qt[d][i]
    __shared__ float KP[64][64];    // phase 1: K^T[d][j]; phase 2: P[i][j]
    __shared__ float Vs[64][DH];    // Vs[j][d]

    const int qt  = (gridDim.x - 1) - blockIdx.x;  // long blocks first
    const int h   = blockIdx.y;
    const int b   = blockIdx.z;
    const int tid = threadIdx.x;
    const int tm  = tid >> 3;       // 0..7  (q-row group)
    const int tn  = tid & 7;        // 0..7  (col group)

    const size_t baseT = ((size_t)b * Hh + h) * (size_t)DH * Tt;  // [d][t]
    const size_t baseN = ((size_t)b * Hh + h) * (size_t)Tt * DH;  // [t][d]
    const float* QT = g_q + baseT;
    const float* KT = g_k + baseT;
    const float* Vh = g_v + baseN;

    float o[8][8];
#pragma unroll
    for (int i = 0; i < 8; i++)
#pragma unroll
        for (int j = 0; j < 8; j++) o[i][j] = 0.f;

    // Load Q^T tile once: rows d (64), cols i (64). 1024 float4 / 64 thr = 16.
#pragma unroll
    for (int l = 0; l < 16; l++) {
        const int f = tid + l * 64;
        const int r = f >> 4;
        const int c = (f & 15) << 2;
        *(float4*)&Qt[r][c] = *(const float4*)&QT[(size_t)r * Tt + qt * 64 + c];
    }

    for (int kt = 0; kt <= qt; kt++) {
        __syncthreads();   // prior iter done with KP (as P) and Vs
        // Load K^T tile (rows d) and V tile (rows j), both row-major float4.
#pragma unroll
        for (int l = 0; l < 16; l++) {
            const int f = tid + l * 64;
            const int r = f >> 4;
            const int c = (f & 15) << 2;
            *(float4*)&KP[r][c] = *(const float4*)&KT[(size_t)r * Tt + kt * 64 + c];
            *(float4*)&Vs[r][c] = *(const float4*)&Vh[(size_t)(kt * 64 + r) * DH + c];
        }
        __syncthreads();

        // S = Qscaled . K^T : 8x8 per thread over d = 0..63.
        float s[8][8];
#pragma unroll
        for (int i = 0; i < 8; i++)
#pragma unroll
            for (int j = 0; j < 8; j++) s[i][j] = 0.f;

#pragma unroll 8
        for (int d = 0; d < DH; d++) {
            float a[8], bb[8];
            *(float4*)&a[0]  = *(const float4*)&Qt[d][tm * 8];
            *(float4*)&a[4]  = *(const float4*)&Qt[d][tm * 8 + 4];
            *(float4*)&bb[0] = *(const float4*)&KP[d][tn * 8];
            *(float4*)&bb[4] = *(const float4*)&KP[d][tn * 8 + 4];
#pragma unroll
            for (int ii = 0; ii < 8; ii++)
#pragma unroll
                for (int jj = 0; jj < 8; jj++)
                    s[ii][jj] += a[ii] * bb[jj];
        }
        __syncthreads();   // everyone done reading KP as K^T

        // ReLU + causal mask on diagonal tile; write P into KP.
        const bool diag = (kt == qt);
#pragma unroll
        for (int ii = 0; ii < 8; ii++) {
            const int qi = tm * 8 + ii;
            float v[8];
#pragma unroll
            for (int jj = 0; jj < 8; jj++) {
                float x = fmaxf(s[ii][jj], 0.f);
                if (diag && (tn * 8 + jj > qi)) x = 0.f;
                v[jj] = x;
            }
            *(float4*)&KP[qi][tn * 8]     = *(float4*)&v[0];
            *(float4*)&KP[qi][tn * 8 + 4] = *(float4*)&v[4];
        }
        __syncthreads();

        // O += P . V : 8x8 per thread over j = 0..63.
#pragma unroll 4
        for (int j = 0; j < 64; j++) {
            float p[8], v[8];
#pragma unroll
            for (int ii = 0; ii < 8; ii++) p[ii] = KP[tm * 8 + ii][j];  // broadcast
            *(float4*)&v[0] = *(const float4*)&Vs[j][tn * 8];
            *(float4*)&v[4] = *(const float4*)&Vs[j][tn * 8 + 4];
#pragma unroll
            for (int ii = 0; ii < 8; ii++)
#pragma unroll
                for (int jj = 0; jj < 8; jj++)
                    o[ii][jj] += p[ii] * v[jj];
        }
    }

    // Write O: out[b][t][h*64 + d], t = qt*64 + tm*8 + ii, d = tn*8 + jj.
    float* op = out + ((size_t)b * Tt + (size_t)qt * 64 + tm * 8) * Cc + h * DH + tn * 8;
#pragma unroll
    for (int ii = 0; ii < 8; ii++) {
        *(float4*)&op[(size_t)ii * Cc]     = make_float4(o[ii][0], o[ii][1], o[ii][2], o[ii][3]);
        *(float4*)&op[(size_t)ii * Cc + 4] = make_float4(o[ii][4], o[ii][5], o[ii][6], o[ii][7]);
    }
}

// ---------------------------------------------------------------------------
extern "C" void kernel_launch(void* const* d_in, const int* in_sizes, int n_in,
                              void* d_out, int out_size)
{
    const float* x    = (const float*)d_in[0];
    const float* W    = (const float*)d_in[1];
    const float* bias = (const float*)d_in[2];
    float* out        = (float*)d_out;
    (void)in_sizes; (void)n_in; (void)out_size;

    dim3 g1(N3 / 128, Mm / 128);    // (18, 64)
    qkv_gemm<<<g1, 256>>>(x, W, bias);

    dim3 g2(Tt / 64, Hh, Bb);       // (32, 12, 4)
    attn_kernel<<<g2, 64>>>(out);
}

// round 4
// speedup vs baseline: 2.8630x; 2.4272x over previous
#include <cuda_runtime.h>
#include <cuda_bf16.h>
#include <cstdint>

// Problem constants (fixed by setup_inputs)
#define Bb 4
#define Tt 2048
#define Cc 768
#define Hh 12
#define DH 64
#define Mm (Bb * Tt)      // 8192
#define N3 (3 * Cc)       // 2304

// ---------------------------------------------------------------------------
// Device scratch: bf16 hi/lo splits.
// x:[M,K], W:[K,N] (natural layouts). q/k/v: [B,H,T,D].
// ---------------------------------------------------------------------------
__device__ __nv_bfloat16 g_xh[(size_t)Mm * Cc], g_xl[(size_t)Mm * Cc];
__device__ __nv_bfloat16 g_wh[(size_t)Cc * N3], g_wl[(size_t)Cc * N3];
__device__ __nv_bfloat16 g_qh[(size_t)Bb * Hh * Tt * DH], g_ql[(size_t)Bb * Hh * Tt * DH];
__device__ __nv_bfloat16 g_kh[(size_t)Bb * Hh * Tt * DH], g_kl[(size_t)Bb * Hh * Tt * DH];
__device__ __nv_bfloat16 g_vh[(size_t)Bb * Hh * Tt * DH], g_vl[(size_t)Bb * Hh * Tt * DH];

// ---------------------------------------------------------------------------
// Helpers
// ---------------------------------------------------------------------------
__device__ __forceinline__ uint32_t smem_u32(const void* p) {
    uint32_t a;
    asm("{ .reg .u64 t; cvta.to.shared.u64 t, %1; cvt.u32.u64 %0, t; }"
        : "=r"(a) : "l"(p));
    return a;
}

__device__ __forceinline__ void ldsm4(uint32_t r[4], uint32_t a) {
    asm volatile("ldmatrix.sync.aligned.m8n8.x4.shared.b16 {%0,%1,%2,%3}, [%4];"
                 : "=r"(r[0]), "=r"(r[1]), "=r"(r[2]), "=r"(r[3]) : "r"(a));
}
__device__ __forceinline__ void ldsm4t(uint32_t r[4], uint32_t a) {
    asm volatile("ldmatrix.sync.aligned.m8n8.x4.trans.shared.b16 {%0,%1,%2,%3}, [%4];"
                 : "=r"(r[0]), "=r"(r[1]), "=r"(r[2]), "=r"(r[3]) : "r"(a));
}

// D = A(bf16 16x16) * B(bf16 16x8) + D, fp32 accum.
__device__ __forceinline__ void mma16816(float* c, const uint32_t* a, uint32_t b0, uint32_t b1) {
    asm volatile(
        "mma.sync.aligned.m16n8k16.row.col.f32.bf16.bf16.f32 "
        "{%0,%1,%2,%3}, {%4,%5,%6,%7}, {%8,%9}, {%0,%1,%2,%3};"
        : "+f"(c[0]), "+f"(c[1]), "+f"(c[2]), "+f"(c[3])
        : "r"(a[0]), "r"(a[1]), "r"(a[2]), "r"(a[3]), "r"(b0), "r"(b1));
}

__device__ __forceinline__ uint32_t pack_bf16(float x, float y) {
    __nv_bfloat162 t = __floats2bfloat162_rn(x, y);   // .x = low halfword
    return *(uint32_t*)&t;
}
__device__ __forceinline__ void split_pack(float x0, float x1, uint32_t& hi, uint32_t& lo) {
    __nv_bfloat16 h0 = __float2bfloat16_rn(x0), h1 = __float2bfloat16_rn(x1);
    hi = ((uint32_t)*(uint16_t*)&h1 << 16) | *(uint16_t*)&h0;
    __nv_bfloat16 l0 = __float2bfloat16_rn(x0 - __bfloat162float(h0));
    __nv_bfloat16 l1 = __float2bfloat16_rn(x1 - __bfloat162float(h1));
    lo = ((uint32_t)*(uint16_t*)&l1 << 16) | *(uint16_t*)&l0;
}

// 128B-row swizzle: XOR row low bits into 16B-chunk index (conflict-free ldmatrix)
#define SWZ(row, byteoff) ((byteoff) ^ (((row) & 7) << 4))

// ---------------------------------------------------------------------------
// Conversion kernels: fp32 -> (hi, lo) bf16
// ---------------------------------------------------------------------------
__global__ __launch_bounds__(256) void cvt_x(const float* __restrict__ x) {
    const size_t base = ((size_t)blockIdx.x * 256 + threadIdx.x) * 4;
    float4 v = *(const float4*)&x[base];
    uint32_t h01, l01, h23, l23;
    split_pack(v.x, v.y, h01, l01);
    split_pack(v.z, v.w, h23, l23);
    *(uint2*)&g_xh[base] = make_uint2(h01, h23);
    *(uint2*)&g_xl[base] = make_uint2(l01, l23);
}
__global__ __launch_bounds__(256) void cvt_w(const float* __restrict__ W) {
    const size_t base = ((size_t)blockIdx.x * 256 + threadIdx.x) * 4;
    float4 v = *(const float4*)&W[base];
    uint32_t h01, l01, h23, l23;
    split_pack(v.x, v.y, h01, l01);
    split_pack(v.z, v.w, h23, l23);
    *(uint2*)&g_wh[base] = make_uint2(h01, h23);
    *(uint2*)&g_wl[base] = make_uint2(l01, l23);
}

// ---------------------------------------------------------------------------
// Kernel 1: qkv = x @ W + b via mma.sync bf16x3 split.
// 128x128 block, 8 warps (2m x 4n), warp tile 64x32, BK=16, double-buffered.
// A smem: rows padded to 48B. B smem: [16][128] bf16, swizzled.
// Epilogue: bias (+0.125 scale for Q), split to bf16 hi/lo, store [B,H,T,D].
// ---------------------------------------------------------------------------
__global__ __launch_bounds__(256) void qkv_mma(const float* __restrict__ bias) {
    __shared__ __align__(128) uint8_t smA[2][2][128 * 48];   // [buf][split]
    __shared__ __align__(128) uint8_t smB[2][2][16 * 256];

    const int tid = threadIdx.x;
    const int l   = tid & 31;
    const int w   = tid >> 5;
    const int wm  = w >> 2;          // 0..1
    const int wn  = w & 3;           // 0..3
    const int m0  = blockIdx.y * 128;
    const int n0  = blockIdx.x * 128;

    float acc[4][4][4];
#pragma unroll
    for (int i = 0; i < 4; i++)
#pragma unroll
        for (int j = 0; j < 4; j++)
#pragma unroll
            for (int r = 0; r < 4; r++) acc[i][j][r] = 0.f;

    // global->smem copy coords
    const int arow  = tid >> 1, ahalf = tid & 1;
    const int brow  = tid >> 4, bc16  = tid & 15;
    const size_t agoff = (size_t)(m0 + arow) * Cc + ahalf * 8;
    const size_t bgoff = (size_t)brow * N3 + n0 + bc16 * 8;
    const int aso = arow * 48 + ahalf * 16;
    const int bso = (brow * 256 + bc16 * 16) ^ ((brow & 7) << 4);

    const uint32_t uA = smem_u32(smA);
    const uint32_t uB = smem_u32(smB);

    // ldmatrix coords
    const int a_row = wm * 64 + (l & 15);            // + mt*16
    const int a_cb  = (l >> 4) * 16;                 // k half (bytes)
    const int b_row = (l & 15);                      // k row
    const int b_cbb = (wn * 32) * 2 + (l >> 4) * 16; // + g*32 bytes

    // prologue
    *(uint4*)(smA[0][0] + aso) = *(const uint4*)&g_xh[agoff];
    *(uint4*)(smA[0][1] + aso) = *(const uint4*)&g_xl[agoff];
    *(uint4*)(smB[0][0] + bso) = *(const uint4*)&g_wh[bgoff];
    *(uint4*)(smB[0][1] + bso) = *(const uint4*)&g_wl[bgoff];
    __syncthreads();

    for (int kb = 0; kb < Cc / 16; kb++) {
        const int cur = kb & 1, nxt = cur ^ 1;
        uint4 pa0, pa1, pb0, pb1;
        const bool pre = (kb < Cc / 16 - 1);
        if (pre) {
            const size_t ao = agoff + (size_t)(kb + 1) * 16;
            const size_t bo = bgoff + (size_t)(kb + 1) * 16 * N3;
            pa0 = *(const uint4*)&g_xh[ao];
            pa1 = *(const uint4*)&g_xl[ao];
            pb0 = *(const uint4*)&g_wh[bo];
            pb1 = *(const uint4*)&g_wl[bo];
        }

        uint32_t fa[2][4][4], fb[2][2][4];
#pragma unroll
        for (int s = 0; s < 2; s++) {
            const uint32_t ab = uA + (cur * 2 + s) * 128 * 48;
#pragma unroll
            for (int mt = 0; mt < 4; mt++)
                ldsm4(fa[s][mt], ab + (a_row + mt * 16) * 48 + a_cb);
            const uint32_t bb = uB + (cur * 2 + s) * 16 * 256;
#pragma unroll
            for (int g = 0; g < 2; g++)
                ldsm4t(fb[s][g], bb + ((b_row * 256 + b_cbb + g * 32) ^ ((b_row & 7) << 4)));
        }

#pragma unroll
        for (int mt = 0; mt < 4; mt++)
#pragma unroll
            for (int nt = 0; nt < 4; nt++) {
                const int g = nt >> 1, i2 = (nt & 1) * 2;
                mma16816(acc[mt][nt], fa[0][mt], fb[0][g][i2], fb[0][g][i2 + 1]);
                mma16816(acc[mt][nt], fa[0][mt], fb[1][g][i2], fb[1][g][i2 + 1]);
                mma16816(acc[mt][nt], fa[1][mt], fb[0][g][i2], fb[0][g][i2 + 1]);
            }

        if (pre) {
            *(uint4*)(smA[nxt][0] + aso) = pa0;
            *(uint4*)(smA[nxt][1] + aso) = pa1;
            *(uint4*)(smB[nxt][0] + bso) = pb0;
            *(uint4*)(smB[nxt][1] + bso) = pb1;
        }
        __syncthreads();
    }

    // ---- Epilogue ----
    const int which = n0 / Cc;                  // 0=Q,1=K,2=V (128 | 768)
    const int nloc0 = n0 - which * Cc;
    const float scale = (which == 0) ? 0.125f : 1.0f;
    __nv_bfloat16* dh = (which == 0) ? g_qh : (which == 1) ? g_kh : g_vh;
    __nv_bfloat16* dl = (which == 0) ? g_ql : (which == 1) ? g_kl : g_vl;

    const int mrow = m0 + wm * 64 + (l >> 2);
    const int b_   = mrow >> 11;
#pragma unroll
    for (int mt = 0; mt < 4; mt++) {
        const int t1 = (mrow + mt * 16) & (Tt - 1);
#pragma unroll
        for (int nt = 0; nt < 4; nt++) {
            const int n  = nloc0 + wn * 32 + nt * 8 + 2 * (l & 3);
            const int hh = n >> 6;
            const int d  = n & 63;
            const float b0 = bias[which * Cc + n];
            const float b1 = bias[which * Cc + n + 1];
            uint32_t h01, l01, h23, l23;
            split_pack((acc[mt][nt][0] + b0) * scale, (acc[mt][nt][1] + b1) * scale, h01, l01);
            split_pack((acc[mt][nt][2] + b0) * scale, (acc[mt][nt][3] + b1) * scale, h23, l23);
            const size_t i1 = (((size_t)b_ * Hh + hh) * Tt + t1) * DH + d;
            const size_t i2 = i1 + (size_t)8 * DH;     // row r2 = t1 + 8
            *(uint32_t*)&dh[i1] = h01;  *(uint32_t*)&dl[i1] = l01;
            *(uint32_t*)&dh[i2] = h23;  *(uint32_t*)&dl[i2] = l23;
        }
    }
}

// ---------------------------------------------------------------------------
// Kernel 2: causal ReLU attention via mma.sync bf16x3 split.
// Block = (qt,h,b), 128 thr (4 warps x 16 q-rows). BQ=BK=64, D=64.
// smem: Q/K/V hi+lo tiles, 128B rows, swizzled. 48KB exactly.
// S accum fragments re-pack directly into P's A-operand fragments.
// ---------------------------------------------------------------------------
__global__ __launch_bounds__(128) void attn_mma(float* __restrict__ out)
{
    __shared__ __align__(128) uint8_t smQ[2][64 * 128];
    __shared__ __align__(128) uint8_t smK[2][64 * 128];
    __shared__ __align__(128) uint8_t smV[2][64 * 128];

    const int tid = threadIdx.x;
    const int l   = tid & 31;
    const int w   = tid >> 5;                       // q-row group
    const int qt  = (gridDim.x - 1) - blockIdx.x;   // long blocks first
    const int h   = blockIdx.y;
    const int b   = blockIdx.z;

    const size_t hb = ((size_t)b * Hh + h) * (size_t)Tt * DH;

    const uint32_t uQ = smem_u32(smQ);
    const uint32_t uK = smem_u32(smK);
    const uint32_t uV = smem_u32(smV);

    // ---- load Q tile (both splits) ----
#pragma unroll
    for (int i = 0; i < 4; i++) {
        const int c   = tid + i * 128;     // 0..511
        const int row = c >> 3;
        const int c16 = c & 7;
        const size_t g = hb + (size_t)(qt * 64 + row) * DH + c16 * 8;
        const int so = SWZ(row, row * 128 + c16 * 16);
        *(uint4*)(smQ[0] + so) = *(const uint4*)&g_qh[g];
        *(uint4*)(smQ[1] + so) = *(const uint4*)&g_ql[g];
    }
    __syncthreads();

    // ---- extract Q fragments (persist all kt) ----
    uint32_t fq[2][4][4];
    {
        const int row = w * 16 + (l & 15);
#pragma unroll
        for (int s = 0; s < 2; s++)
#pragma unroll
            for (int ks = 0; ks < 4; ks++) {
                const int cb = (ks * 16 + (l >> 4) * 8) * 2;
                ldsm4(fq[s][ks], uQ + s * 8192 + SWZ(row, row * 128 + cb));
            }
    }

    float o[8][4];
#pragma unroll
    for (int i = 0; i < 8; i++)
#pragma unroll
        for (int r = 0; r < 4; r++) o[i][r] = 0.f;

    for (int kt = 0; kt <= qt; kt++) {
        __syncthreads();   // prior iter done reading K/V
#pragma unroll
        for (int i = 0; i < 4; i++) {
            const int c   = tid + i * 128;
            const int row = c >> 3;
            const int c16 = c & 7;
            const size_t g = hb + (size_t)(kt * 64 + row) * DH + c16 * 8;
            const int so = SWZ(row, row * 128 + c16 * 16);
            *(uint4*)(smK[0] + so) = *(const uint4*)&g_kh[g];
            *(uint4*)(smK[1] + so) = *(const uint4*)&g_kl[g];
            *(uint4*)(smV[0] + so) = *(const uint4*)&g_vh[g];
            *(uint4*)(smV[1] + so) = *(const uint4*)&g_vl[g];
        }
        __syncthreads();

        // ---- S = Q . K^T ----
        float s[8][4];
#pragma unroll
        for (int i = 0; i < 8; i++)
#pragma unroll
            for (int r = 0; r < 4; r++) s[i][r] = 0.f;

#pragma unroll
        for (int ks = 0; ks < 4; ks++) {
            uint32_t fk[2][4][4];
            const int nrow = (l & 7) + 8 * (l >> 4);
            const int cb   = (ks * 16 + 8 * ((l >> 3) & 1)) * 2;
#pragma unroll
            for (int sp = 0; sp < 2; sp++)
#pragma unroll
                for (int g = 0; g < 4; g++) {
                    const int rr = g * 16 + nrow;
                    ldsm4(fk[sp][g], uK + sp * 8192 + SWZ(rr, rr * 128 + cb));
                }
#pragma unroll
            for (int nt = 0; nt < 8; nt++) {
                const int g = nt >> 1, i2 = (nt & 1) * 2;
                mma16816(s[nt], fq[0][ks], fk[0][g][i2], fk[0][g][i2 + 1]);
                mma16816(s[nt], fq[0][ks], fk[1][g][i2], fk[1][g][i2 + 1]);
                mma16816(s[nt], fq[1][ks], fk[0][g][i2], fk[0][g][i2 + 1]);
            }
        }

        // ---- ReLU + causal mask + split into P A-fragments ----
        uint32_t ph[4][4], pl[4][4];
        const bool diag = (kt == qt);
        const int rowg = qt * 64 + w * 16 + (l >> 2);
#pragma unroll
        for (int nt = 0; nt < 8; nt++) {
            const int colg = kt * 64 + nt * 8 + 2 * (l & 3);
            float v0 = fmaxf(s[nt][0], 0.f);
            float v1 = fmaxf(s[nt][1], 0.f);
            float v2 = fmaxf(s[nt][2], 0.f);
            float v3 = fmaxf(s[nt][3], 0.f);
            if (diag) {
                if (colg     > rowg)     v0 = 0.f;
                if (colg + 1 > rowg)     v1 = 0.f;
                if (colg     > rowg + 8) v2 = 0.f;
                if (colg + 1 > rowg + 8) v3 = 0.f;
            }
            const int js = nt >> 1, pos = (nt & 1) * 2;
            split_pack(v0, v1, ph[js][pos],     pl[js][pos]);
            split_pack(v2, v3, ph[js][pos + 1], pl[js][pos + 1]);
        }

        // ---- O += P . V ----
#pragma unroll
        for (int js = 0; js < 4; js++) {
            uint32_t fv[2][4][4];
            const int vrow = js * 16 + (l & 15);
#pragma unroll
            for (int sp = 0; sp < 2; sp++)
#pragma unroll
                for (int g = 0; g < 4; g++) {
                    const int cb = (g * 16 + (l >> 4) * 8) * 2;
                    ldsm4t(fv[sp][g], uV + sp * 8192 + SWZ(vrow, vrow * 128 + cb));
                }
#pragma unroll
            for (int dt = 0; dt < 8; dt++) {
                const int g = dt >> 1, i2 = (dt & 1) * 2;
                mma16816(o[dt], ph[js], fv[0][g][i2], fv[0][g][i2 + 1]);
                mma16816(o[dt], ph[js], fv[1][g][i2], fv[1][g][i2 + 1]);
                mma16816(o[dt], pl[js], fv[0][g][i2], fv[0][g][i2 + 1]);
            }
        }
    }

    // ---- store O ----
    const int r1 = qt * 64 + w * 16 + (l >> 2);
#pragma unroll
    for (int dt = 0; dt < 8; dt++) {
        const int col = h * DH + dt * 8 + 2 * (l & 3);
        *(float2*)&out[((size_t)b * Tt + r1) * Cc + col]     = make_float2(o[dt][0], o[dt][1]);
        *(float2*)&out[((size_t)b * Tt + r1 + 8) * Cc + col] = make_float2(o[dt][2], o[dt][3]);
    }
}

// ---------------------------------------------------------------------------
extern "C" void kernel_launch(void* const* d_in, const int* in_sizes, int n_in,
                              void* d_out, int out_size)
{
    const float* x    = (const float*)d_in[0];
    const float* W    = (const float*)d_in[1];
    const float* bias = (const float*)d_in[2];
    float* out        = (float*)d_out;
    (void)in_sizes; (void)n_in; (void)out_size;

    cvt_x<<<(Mm * Cc) / 1024, 256>>>(x);
    cvt_w<<<(Cc * N3) / 1024, 256>>>(W);

    dim3 g1(N3 / 128, Mm / 128);    // (18, 64)
    qkv_mma<<<g1, 256>>>(bias);

    dim3 g2(Tt / 64, Hh, Bb);       // (32, 12, 4)
    attn_mma<<<g2, 128>>>(out);
}

// round 5
// speedup vs baseline: 3.1417x; 1.0973x over previous
#include <cuda_runtime.h>
#include <cuda_bf16.h>
#include <cstdint>

// Problem constants (fixed by setup_inputs)
#define Bb 4
#define Tt 2048
#define Cc 768
#define Hh 12
#define DH 64
#define Mm (Bb * Tt)      // 8192
#define N3 (3 * Cc)       // 2304

// ---------------------------------------------------------------------------
// Device scratch: bf16 hi/lo splits.
// ---------------------------------------------------------------------------
__device__ __nv_bfloat16 g_xh[(size_t)Mm * Cc], g_xl[(size_t)Mm * Cc];
__device__ __nv_bfloat16 g_wh[(size_t)Cc * N3], g_wl[(size_t)Cc * N3];
__device__ __nv_bfloat16 g_qh[(size_t)Bb * Hh * Tt * DH], g_ql[(size_t)Bb * Hh * Tt * DH];
__device__ __nv_bfloat16 g_kh[(size_t)Bb * Hh * Tt * DH], g_kl[(size_t)Bb * Hh * Tt * DH];
__device__ __nv_bfloat16 g_vh[(size_t)Bb * Hh * Tt * DH], g_vl[(size_t)Bb * Hh * Tt * DH];

// ---------------------------------------------------------------------------
// Helpers
// ---------------------------------------------------------------------------
__device__ __forceinline__ uint32_t smem_u32(const void* p) {
    uint32_t a;
    asm("{ .reg .u64 t; cvta.to.shared.u64 t, %1; cvt.u32.u64 %0, t; }"
        : "=r"(a) : "l"(p));
    return a;
}
__device__ __forceinline__ void ldsm4(uint32_t r[4], uint32_t a) {
    asm volatile("ldmatrix.sync.aligned.m8n8.x4.shared.b16 {%0,%1,%2,%3}, [%4];"
                 : "=r"(r[0]), "=r"(r[1]), "=r"(r[2]), "=r"(r[3]) : "r"(a));
}
__device__ __forceinline__ void ldsm4t(uint32_t r[4], uint32_t a) {
    asm volatile("ldmatrix.sync.aligned.m8n8.x4.trans.shared.b16 {%0,%1,%2,%3}, [%4];"
                 : "=r"(r[0]), "=r"(r[1]), "=r"(r[2]), "=r"(r[3]) : "r"(a));
}
__device__ __forceinline__ void mma16816(float* c, const uint32_t* a, uint32_t b0, uint32_t b1) {
    asm volatile(
        "mma.sync.aligned.m16n8k16.row.col.f32.bf16.bf16.f32 "
        "{%0,%1,%2,%3}, {%4,%5,%6,%7}, {%8,%9}, {%0,%1,%2,%3};"
        : "+f"(c[0]), "+f"(c[1]), "+f"(c[2]), "+f"(c[3])
        : "r"(a[0]), "r"(a[1]), "r"(a[2]), "r"(a[3]), "r"(b0), "r"(b1));
}
__device__ __forceinline__ void split_pack(float x0, float x1, uint32_t& hi, uint32_t& lo) {
    __nv_bfloat16 h0 = __float2bfloat16_rn(x0), h1 = __float2bfloat16_rn(x1);
    hi = ((uint32_t)*(uint16_t*)&h1 << 16) | *(uint16_t*)&h0;
    __nv_bfloat16 l0 = __float2bfloat16_rn(x0 - __bfloat162float(h0));
    __nv_bfloat16 l1 = __float2bfloat16_rn(x1 - __bfloat162float(h1));
    lo = ((uint32_t)*(uint16_t*)&l1 << 16) | *(uint16_t*)&l0;
}

#define CP16(s, g) \
    asm volatile("cp.async.cg.shared.global [%0], [%1], 16;" :: "r"(s), "l"(g))
#define CP_COMMIT() asm volatile("cp.async.commit_group;" ::: "memory")
#define CP_WAIT0()  asm volatile("cp.async.wait_group 0;" ::: "memory")

// 128B-row swizzle: XOR row low bits into 16B-chunk index
#define SWZ(row, byteoff) ((byteoff) ^ (((row) & 7) << 4))

// ---------------------------------------------------------------------------
// Conversion kernels: fp32 -> (hi, lo) bf16
// ---------------------------------------------------------------------------
__global__ __launch_bounds__(256) void cvt_x(const float* __restrict__ x) {
    const size_t base = ((size_t)blockIdx.x * 256 + threadIdx.x) * 4;
    float4 v = *(const float4*)&x[base];
    uint32_t h01, l01, h23, l23;
    split_pack(v.x, v.y, h01, l01);
    split_pack(v.z, v.w, h23, l23);
    *(uint2*)&g_xh[base] = make_uint2(h01, h23);
    *(uint2*)&g_xl[base] = make_uint2(l01, l23);
}
__global__ __launch_bounds__(256) void cvt_w(const float* __restrict__ W) {
    const size_t base = ((size_t)blockIdx.x * 256 + threadIdx.x) * 4;
    float4 v = *(const float4*)&W[base];
    uint32_t h01, l01, h23, l23;
    split_pack(v.x, v.y, h01, l01);
    split_pack(v.z, v.w, h23, l23);
    *(uint2*)&g_wh[base] = make_uint2(h01, h23);
    *(uint2*)&g_wl[base] = make_uint2(l01, l23);
}

// ---------------------------------------------------------------------------
// Kernel 1: qkv = x @ W + b via mma.sync bf16x3. cp.async double-buffered.
// 128x128 block, 8 warps (2m x 4n), warp tile 64x32, BK=16.
// ---------------------------------------------------------------------------
__global__ __launch_bounds__(256) void qkv_mma(const float* __restrict__ bias) {
    __shared__ __align__(128) uint8_t smA[2][2][128 * 48];   // [buf][split] 24KB
    __shared__ __align__(128) uint8_t smB[2][2][16 * 256];   // [buf][split] 16KB

    const int tid = threadIdx.x;
    const int l   = tid & 31;
    const int w   = tid >> 5;
    const int wm  = w >> 2;          // 0..1
    const int wn  = w & 3;           // 0..3
    const int m0  = blockIdx.y * 128;
    const int n0  = blockIdx.x * 128;

    float acc[4][4][4];
#pragma unroll
    for (int i = 0; i < 4; i++)
#pragma unroll
        for (int j = 0; j < 4; j++)
#pragma unroll
            for (int r = 0; r < 4; r++) acc[i][j][r] = 0.f;

    const uint32_t uA = smem_u32(smA);
    const uint32_t uB = smem_u32(smB);

    // cp.async coords
    const int arow = tid >> 1, ahalf = tid & 1;
    const int brow = tid >> 4, bc16  = tid & 15;
    const uint32_t aso = arow * 48 + ahalf * 16;
    const uint32_t bso = (uint32_t)((brow * 256 + bc16 * 16) ^ ((brow & 7) << 4));
    const size_t agoff = (size_t)(m0 + arow) * Cc + ahalf * 8;
    const size_t bgoff = (size_t)brow * N3 + n0 + bc16 * 8;

#define QKV_ISSUE(kb, buf) do {                                             \
    const size_t _ga = agoff + (size_t)(kb) * 16;                           \
    const size_t _gb = bgoff + (size_t)(kb) * 16 * N3;                      \
    const uint32_t _da = uA + (buf) * 12288 + aso;                          \
    const uint32_t _db = uB + (buf) * 8192 + bso;                           \
    CP16(_da,        g_xh + _ga);                                           \
    CP16(_da + 6144, g_xl + _ga);                                           \
    CP16(_db,        g_wh + _gb);                                           \
    CP16(_db + 4096, g_wl + _gb);                                           \
    CP_COMMIT();                                                            \
} while (0)

    // ldmatrix coords
    const int a_row = wm * 64 + (l & 15);
    const int a_cb  = (l >> 4) * 16;
    const int b_row = (l & 15);
    const int b_cbb = (wn * 32) * 2 + (l >> 4) * 16;

    QKV_ISSUE(0, 0);

    for (int kb = 0; kb < Cc / 16; kb++) {
        const int cur = kb & 1;
        CP_WAIT0();
        __syncthreads();
        if (kb + 1 < Cc / 16) QKV_ISSUE(kb + 1, cur ^ 1);

        uint32_t fa[2][4][4], fb[2][2][4];
#pragma unroll
        for (int s = 0; s < 2; s++) {
            const uint32_t ab = uA + (cur * 2 + s) * 6144;
#pragma unroll
            for (int mt = 0; mt < 4; mt++)
                ldsm4(fa[s][mt], ab + (a_row + mt * 16) * 48 + a_cb);
            const uint32_t bb = uB + (cur * 2 + s) * 4096;
#pragma unroll
            for (int g = 0; g < 2; g++)
                ldsm4t(fb[s][g], bb + ((b_row * 256 + b_cbb + g * 32) ^ ((b_row & 7) << 4)));
        }

#pragma unroll
        for (int mt = 0; mt < 4; mt++)
#pragma unroll
            for (int nt = 0; nt < 4; nt++) {
                const int g = nt >> 1, i2 = (nt & 1) * 2;
                mma16816(acc[mt][nt], fa[0][mt], fb[0][g][i2], fb[0][g][i2 + 1]);
                mma16816(acc[mt][nt], fa[0][mt], fb[1][g][i2], fb[1][g][i2 + 1]);
                mma16816(acc[mt][nt], fa[1][mt], fb[0][g][i2], fb[0][g][i2 + 1]);
            }
    }

    // ---- Epilogue ----
    const int which = n0 / Cc;                  // 0=Q,1=K,2=V
    const int nloc0 = n0 - which * Cc;
    const float scale = (which == 0) ? 0.125f : 1.0f;
    __nv_bfloat16* dh = (which == 0) ? g_qh : (which == 1) ? g_kh : g_vh;
    __nv_bfloat16* dl = (which == 0) ? g_ql : (which == 1) ? g_kl : g_vl;

    const int mrow = m0 + wm * 64 + (l >> 2);
    const int b_   = mrow >> 11;
#pragma unroll
    for (int mt = 0; mt < 4; mt++) {
        const int t1 = (mrow + mt * 16) & (Tt - 1);
#pragma unroll
        for (int nt = 0; nt < 4; nt++) {
            const int n  = nloc0 + wn * 32 + nt * 8 + 2 * (l & 3);
            const int hh = n >> 6;
            const int d  = n & 63;
            const float b0 = bias[which * Cc + n];
            const float b1 = bias[which * Cc + n + 1];
            uint32_t h01, l01, h23, l23;
            split_pack((acc[mt][nt][0] + b0) * scale, (acc[mt][nt][1] + b1) * scale, h01, l01);
            split_pack((acc[mt][nt][2] + b0) * scale, (acc[mt][nt][3] + b1) * scale, h23, l23);
            const size_t i1 = (((size_t)b_ * Hh + hh) * Tt + t1) * DH + d;
            const size_t i2 = i1 + (size_t)8 * DH;
            *(uint32_t*)&dh[i1] = h01;  *(uint32_t*)&dl[i1] = l01;
            *(uint32_t*)&dh[i2] = h23;  *(uint32_t*)&dl[i2] = l23;
        }
    }
}

// ---------------------------------------------------------------------------
// Kernel 2: causal ReLU attention via mma.sync bf16x3.
// Block = (qt,h,b), 128 thr (4 warps x 16 q-rows). BQ=64, BK=32, D=64.
// K/V tiles cp.async double-buffered; Q fragments persist in registers.
// ---------------------------------------------------------------------------
__global__ __launch_bounds__(128) void attn_mma(float* __restrict__ out)
{
    __shared__ __align__(128) uint8_t smQ[2][64 * 128];       // hi/lo 16KB
    __shared__ __align__(128) uint8_t smK[2][2][32 * 128];    // [buf][split] 16KB
    __shared__ __align__(128) uint8_t smV[2][2][32 * 128];    // 16KB

    const int tid = threadIdx.x;
    const int l   = tid & 31;
    const int w   = tid >> 5;
    const int qt  = (gridDim.x - 1) - blockIdx.x;
    const int h   = blockIdx.y;
    const int b   = blockIdx.z;

    const size_t hb = ((size_t)b * Hh + h) * (size_t)Tt * DH;

    const uint32_t uQ = smem_u32(smQ);
    const uint32_t uK = smem_u32(smK);
    const uint32_t uV = smem_u32(smV);

#define ATT_ISSUE(j2, buf) do {                                             \
    _Pragma("unroll")                                                       \
    for (int _i = 0; _i < 2; _i++) {                                        \
        const int _c = tid + _i * 128;                                      \
        const int _row = _c >> 3;                                           \
        const int _c16 = _c & 7;                                            \
        const uint32_t _so = SWZ(_row, _row * 128 + _c16 * 16);             \
        const size_t _g = hb + (size_t)((j2) * 32 + _row) * DH + _c16 * 8;  \
        CP16(uK + (buf) * 8192 + _so,        g_kh + _g);                    \
        CP16(uK + (buf) * 8192 + 4096 + _so, g_kl + _g);                    \
        CP16(uV + (buf) * 8192 + _so,        g_vh + _g);                    \
        CP16(uV + (buf) * 8192 + 4096 + _so, g_vl + _g);                    \
    }                                                                       \
    CP_COMMIT();                                                            \
} while (0)

    // Q tile -> smem (LDG), first K/V tile via cp.async.
#pragma unroll
    for (int i = 0; i < 4; i++) {
        const int c   = tid + i * 128;
        const int row = c >> 3;
        const int c16 = c & 7;
        const size_t g = hb + (size_t)(qt * 64 + row) * DH + c16 * 8;
        const int so = SWZ(row, row * 128 + c16 * 16);
        *(uint4*)(smQ[0] + so) = *(const uint4*)&g_qh[g];
        *(uint4*)(smQ[1] + so) = *(const uint4*)&g_ql[g];
    }
    ATT_ISSUE(0, 0);
    __syncthreads();   // Q visible

    // Q fragments (persist)
    uint32_t fq[2][4][4];
    {
        const int row = w * 16 + (l & 15);
#pragma unroll
        for (int s = 0; s < 2; s++)
#pragma unroll
            for (int ks = 0; ks < 4; ks++) {
                const int cb = (ks * 16 + (l >> 4) * 8) * 2;
                ldsm4(fq[s][ks], uQ + s * 8192 + SWZ(row, row * 128 + cb));
            }
    }

    float o[8][4];
#pragma unroll
    for (int i = 0; i < 8; i++)
#pragma unroll
        for (int r = 0; r < 4; r++) o[i][r] = 0.f;

    const int ntile = 2 * (qt + 1);
    const int rowg  = qt * 64 + w * 16 + (l >> 2);

    for (int j2 = 0; j2 < ntile; j2++) {
        const int cur = j2 & 1;
        CP_WAIT0();
        __syncthreads();
        if (j2 + 1 < ntile) ATT_ISSUE(j2 + 1, cur ^ 1);

        // ---- S = Q . K^T (64 q x 32 k) ----
        float s[4][4];
#pragma unroll
        for (int i = 0; i < 4; i++)
#pragma unroll
            for (int r = 0; r < 4; r++) s[i][r] = 0.f;

#pragma unroll
        for (int ks = 0; ks < 4; ks++) {
            uint32_t fk[2][2][4];
            const int nrow = (l & 7) + 8 * (l >> 4);
            const int cb   = (ks * 16 + 8 * ((l >> 3) & 1)) * 2;
#pragma unroll
            for (int sp = 0; sp < 2; sp++)
#pragma unroll
                for (int g = 0; g < 2; g++) {
                    const int rr = g * 16 + nrow;
                    ldsm4(fk[sp][g], uK + cur * 8192 + sp * 4096 + SWZ(rr, rr * 128 + cb));
                }
#pragma unroll
            for (int nt = 0; nt < 4; nt++) {
                const int g = nt >> 1, i2 = (nt & 1) * 2;
                mma16816(s[nt], fq[0][ks], fk[0][g][i2], fk[0][g][i2 + 1]);
                mma16816(s[nt], fq[0][ks], fk[1][g][i2], fk[1][g][i2 + 1]);
                mma16816(s[nt], fq[1][ks], fk[0][g][i2], fk[0][g][i2 + 1]);
            }
        }

        // ---- ReLU + causal mask + split into P fragments ----
        uint32_t ph[2][4], pl[2][4];
        const bool needmask = (j2 >= 2 * qt);
#pragma unroll
        for (int nt = 0; nt < 4; nt++) {
            const int colg = j2 * 32 + nt * 8 + 2 * (l & 3);
            float v0 = fmaxf(s[nt][0], 0.f);
            float v1 = fmaxf(s[nt][1], 0.f);
            float v2 = fmaxf(s[nt][2], 0.f);
            float v3 = fmaxf(s[nt][3], 0.f);
            if (needmask) {
                if (colg     > rowg)     v0 = 0.f;
                if (colg + 1 > rowg)     v1 = 0.f;
                if (colg     > rowg + 8) v2 = 0.f;
                if (colg + 1 > rowg + 8) v3 = 0.f;
            }
            const int js = nt >> 1, pos = (nt & 1) * 2;
            split_pack(v0, v1, ph[js][pos],     pl[js][pos]);
            split_pack(v2, v3, ph[js][pos + 1], pl[js][pos + 1]);
        }

        // ---- O += P . V (64 q x 64 d, k=32) ----
#pragma unroll
        for (int js = 0; js < 2; js++) {
            uint32_t fv[2][4][4];
            const int vrow = js * 16 + (l & 15);
#pragma unroll
            for (int sp = 0; sp < 2; sp++)
#pragma unroll
                for (int g = 0; g < 4; g++) {
                    const int cb = (g * 16 + (l >> 4) * 8) * 2;
                    ldsm4t(fv[sp][g], uV + cur * 8192 + sp * 4096 + SWZ(vrow, vrow * 128 + cb));
                }
#pragma unroll
            for (int dt = 0; dt < 8; dt++) {
                const int g = dt >> 1, i2 = (dt & 1) * 2;
                mma16816(o[dt], ph[js], fv[0][g][i2], fv[0][g][i2 + 1]);
                mma16816(o[dt], ph[js], fv[1][g][i2], fv[1][g][i2 + 1]);
                mma16816(o[dt], pl[js], fv[0][g][i2], fv[0][g][i2 + 1]);
            }
        }
    }

    // ---- store O ----
    const int r1 = qt * 64 + w * 16 + (l >> 2);
#pragma unroll
    for (int dt = 0; dt < 8; dt++) {
        const int col = h * DH + dt * 8 + 2 * (l & 3);
        *(float2*)&out[((size_t)b * Tt + r1) * Cc + col]     = make_float2(o[dt][0], o[dt][1]);
        *(float2*)&out[((size_t)b * Tt + r1 + 8) * Cc + col] = make_float2(o[dt][2], o[dt][3]);
    }
}

// ---------------------------------------------------------------------------
extern "C" void kernel_launch(void* const* d_in, const int* in_sizes, int n_in,
                              void* d_out, int out_size)
{
    const float* x    = (const float*)d_in[0];
    const float* W    = (const float*)d_in[1];
    const float* bias = (const float*)d_in[2];
    float* out        = (float*)d_out;
    (void)in_sizes; (void)n_in; (void)out_size;

    cvt_x<<<(Mm * Cc) / 1024, 256>>>(x);
    cvt_w<<<(Cc * N3) / 1024, 256>>>(W);

    dim3 g1(N3 / 128, Mm / 128);    // (18, 64)
    qkv_mma<<<g1, 256>>>(bias);

    dim3 g2(Tt / 64, Hh, Bb);       // (32, 12, 4)
    attn_mma<<<g2, 128>>>(out);
}

// round 6
// speedup vs baseline: 3.7166x; 1.1830x over previous
#include <cuda_runtime.h>
#include <cuda_bf16.h>
#include <cstdint>

// Problem constants (fixed by setup_inputs)
#define Bb 4
#define Tt 2048
#define Cc 768
#define Hh 12
#define DH 64
#define Mm (Bb * Tt)      // 8192
#define N3 (3 * Cc)       // 2304
#define NKSTEP (Cc / 16)  // 48

// ---------------------------------------------------------------------------
// Device scratch: bf16 hi/lo splits.
// x splits are stored TRANSPOSED: [K][M]. W splits natural [K][N].
// q/k/v: [B,H,T,D].
// ---------------------------------------------------------------------------
__device__ __nv_bfloat16 g_xh[(size_t)Cc * Mm], g_xl[(size_t)Cc * Mm];
__device__ __nv_bfloat16 g_wh[(size_t)Cc * N3], g_wl[(size_t)Cc * N3];
__device__ __nv_bfloat16 g_qh[(size_t)Bb * Hh * Tt * DH], g_ql[(size_t)Bb * Hh * Tt * DH];
__device__ __nv_bfloat16 g_kh[(size_t)Bb * Hh * Tt * DH], g_kl[(size_t)Bb * Hh * Tt * DH];
__device__ __nv_bfloat16 g_vh[(size_t)Bb * Hh * Tt * DH], g_vl[(size_t)Bb * Hh * Tt * DH];

// ---------------------------------------------------------------------------
// Helpers
// ---------------------------------------------------------------------------
__device__ __forceinline__ uint32_t smem_u32(const void* p) {
    uint32_t a;
    asm("{ .reg .u64 t; cvta.to.shared.u64 t, %1; cvt.u32.u64 %0, t; }"
        : "=r"(a) : "l"(p));
    return a;
}
__device__ __forceinline__ void ldsm4(uint32_t r[4], uint32_t a) {
    asm volatile("ldmatrix.sync.aligned.m8n8.x4.shared.b16 {%0,%1,%2,%3}, [%4];"
                 : "=r"(r[0]), "=r"(r[1]), "=r"(r[2]), "=r"(r[3]) : "r"(a));
}
__device__ __forceinline__ void ldsm4t(uint32_t r[4], uint32_t a) {
    asm volatile("ldmatrix.sync.aligned.m8n8.x4.trans.shared.b16 {%0,%1,%2,%3}, [%4];"
                 : "=r"(r[0]), "=r"(r[1]), "=r"(r[2]), "=r"(r[3]) : "r"(a));
}
__device__ __forceinline__ void mma16816(float* c, const uint32_t* a, uint32_t b0, uint32_t b1) {
    asm volatile(
        "mma.sync.aligned.m16n8k16.row.col.f32.bf16.bf16.f32 "
        "{%0,%1,%2,%3}, {%4,%5,%6,%7}, {%8,%9}, {%0,%1,%2,%3};"
        : "+f"(c[0]), "+f"(c[1]), "+f"(c[2]), "+f"(c[3])
        : "r"(a[0]), "r"(a[1]), "r"(a[2]), "r"(a[3]), "r"(b0), "r"(b1));
}
__device__ __forceinline__ void split_pack(float x0, float x1, uint32_t& hi, uint32_t& lo) {
    __nv_bfloat16 h0 = __float2bfloat16_rn(x0), h1 = __float2bfloat16_rn(x1);
    hi = ((uint32_t)*(uint16_t*)&h1 << 16) | *(uint16_t*)&h0;
    __nv_bfloat16 l0 = __float2bfloat16_rn(x0 - __bfloat162float(h0));
    __nv_bfloat16 l1 = __float2bfloat16_rn(x1 - __bfloat162float(h1));
    lo = ((uint32_t)*(uint16_t*)&l1 << 16) | *(uint16_t*)&l0;
}

#define CP16(s, g) \
    asm volatile("cp.async.cg.shared.global [%0], [%1], 16;" :: "r"(s), "l"(g))
#define CP_COMMIT() asm volatile("cp.async.commit_group;" ::: "memory")
#define CP_WAIT0()  asm volatile("cp.async.wait_group 0;" ::: "memory")
#define CP_WAIT1()  asm volatile("cp.async.wait_group 1;" ::: "memory")

// swizzle: XOR row low bits into 16B-chunk index (row-size-agnostic, 128B period)
#define SWZ(row, byteoff) ((byteoff) ^ (((row) & 7) << 4))

// ---------------------------------------------------------------------------
// cvt_x: fp32 x[M][K] -> bf16 hi/lo TRANSPOSED [K][M]
// ---------------------------------------------------------------------------
__global__ __launch_bounds__(256) void cvt_x(const float* __restrict__ x) {
    __shared__ float S[64][65];
    const int m0 = blockIdx.x * 64, k0 = blockIdx.y * 64;
    const int tid = threadIdx.x;
#pragma unroll
    for (int i = 0; i < 4; i++) {
        const int c = tid + i * 256;         // 0..1023
        const int row = c >> 4;              // m 0..63
        const int c4 = (c & 15) * 4;         // k
        float4 v = *(const float4*)&x[(size_t)(m0 + row) * Cc + k0 + c4];
        S[row][c4] = v.x; S[row][c4 + 1] = v.y; S[row][c4 + 2] = v.z; S[row][c4 + 3] = v.w;
    }
    __syncthreads();
#pragma unroll
    for (int i = 0; i < 2; i++) {
        const int c = tid + i * 256;         // 0..511
        const int k = c >> 3;                // 0..63
        const int mc = c & 7;                // m-chunk of 8
        uint32_t hw[4], lw[4];
#pragma unroll
        for (int e = 0; e < 4; e++)
            split_pack(S[mc * 8 + 2 * e][k], S[mc * 8 + 2 * e + 1][k], hw[e], lw[e]);
        const size_t g = (size_t)(k0 + k) * Mm + m0 + mc * 8;
        *(uint4*)&g_xh[g] = make_uint4(hw[0], hw[1], hw[2], hw[3]);
        *(uint4*)&g_xl[g] = make_uint4(lw[0], lw[1], lw[2], lw[3]);
    }
}
__global__ __launch_bounds__(256) void cvt_w(const float* __restrict__ W) {
    const size_t base = ((size_t)blockIdx.x * 256 + threadIdx.x) * 4;
    float4 v = *(const float4*)&W[base];
    uint32_t h01, l01, h23, l23;
    split_pack(v.x, v.y, h01, l01);
    split_pack(v.z, v.w, h23, l23);
    *(uint2*)&g_wh[base] = make_uint2(h01, h23);
    *(uint2*)&g_wl[base] = make_uint2(l01, l23);
}

// ---------------------------------------------------------------------------
// Kernel 1: qkv = x @ W + b via mma.sync bf16x3.
// 128(m) x 256(n) block tile, BK=16, 256 thr, 8 warps (2m x 4n), warp 64x64.
// smem/stage: A^T(k-major) hi/lo 4KB+4KB, B hi/lo 8KB+8KB = 24KB; x2 = 48KB.
// ---------------------------------------------------------------------------
__global__ __launch_bounds__(256) void qkv_mma(const float* __restrict__ bias) {
    __shared__ __align__(128) uint8_t sm[49152];
    // stage s at s*24576: A_hi +0, A_lo +4096, B_hi +8192, B_lo +16384

    const int tid = threadIdx.x;
    const int l   = tid & 31;
    const int w   = tid >> 5;
    const int wm  = w >> 2;          // 0..1 (64 m each)
    const int wn  = w & 3;           // 0..3 (64 n each)
    const int m0  = blockIdx.y * 128;
    const int n0  = blockIdx.x * 256;

    const uint32_t uS = smem_u32(sm);

    float acc[4][8][4];
#pragma unroll
    for (int i = 0; i < 4; i++)
#pragma unroll
        for (int j = 0; j < 8; j++)
#pragma unroll
            for (int r = 0; r < 4; r++) acc[i][j][r] = 0.f;

    // cp.async coords
    const int ar = tid >> 4, ac = tid & 15;          // A: 16 rows x 16 chunks
    const uint32_t aso = (uint32_t)SWZ(ar, ar * 256 + ac * 16);
    const int br0 = tid >> 5, bc0 = tid & 31;        // B: 16 rows x 32 chunks, 2/thread
    const int br1 = (tid + 256) >> 5, bc1 = tid & 31;
    const uint32_t bso0 = (uint32_t)SWZ(br0, br0 * 512 + bc0 * 16);
    const uint32_t bso1 = (uint32_t)SWZ(br1, br1 * 512 + bc1 * 16);

#define QKV_ISSUE(kb, buf) do {                                               \
    const int _k0 = (kb) * 16;                                                \
    const uint32_t _b = uS + (buf) * 24576;                                   \
    const size_t _ga = (size_t)(_k0 + ar) * Mm + m0 + ac * 8;                 \
    CP16(_b + aso,        g_xh + _ga);                                        \
    CP16(_b + 4096 + aso, g_xl + _ga);                                        \
    const size_t _gb0 = (size_t)(_k0 + br0) * N3 + n0 + bc0 * 8;              \
    const size_t _gb1 = (size_t)(_k0 + br1) * N3 + n0 + bc1 * 8;              \
    CP16(_b + 8192 + bso0,  g_wh + _gb0);                                     \
    CP16(_b + 16384 + bso0, g_wl + _gb0);                                     \
    CP16(_b + 8192 + bso1,  g_wh + _gb1);                                     \
    CP16(_b + 16384 + bso1, g_wl + _gb1);                                     \
    CP_COMMIT();                                                              \
} while (0)

    // ldsm coords
    const int arow = (l & 7) + 8 * (l >> 4);               // A smem k-row
    const int abyt = wm * 128 + ((l >> 3) & 1) * 16;       // + mt*32
    const int brow = (l & 15);                             // B smem k-row
    const int bbyt = wn * 128 + (l >> 4) * 16;             // + g*32

    QKV_ISSUE(0, 0);

    for (int kb = 0; kb < NKSTEP; kb++) {
        const int cur = kb & 1;
        CP_WAIT0();
        __syncthreads();
        if (kb + 1 < NKSTEP) QKV_ISSUE(kb + 1, cur ^ 1);

        const uint32_t sb = uS + cur * 24576;
        uint32_t fa[2][4][4], fb[2][4][4];
#pragma unroll
        for (int sp = 0; sp < 2; sp++) {
#pragma unroll
            for (int mt = 0; mt < 4; mt++)
                ldsm4t(fa[sp][mt], sb + sp * 4096 + SWZ(arow, arow * 256 + abyt + mt * 32));
#pragma unroll
            for (int g = 0; g < 4; g++)
                ldsm4t(fb[sp][g], sb + 8192 + sp * 8192 + SWZ(brow, brow * 512 + bbyt + g * 32));
        }

#pragma unroll
        for (int mt = 0; mt < 4; mt++)
#pragma unroll
            for (int nt = 0; nt < 8; nt++) {
                const int g = nt >> 1, i2 = (nt & 1) * 2;
                mma16816(acc[mt][nt], fa[0][mt], fb[0][g][i2], fb[0][g][i2 + 1]);
                mma16816(acc[mt][nt], fa[0][mt], fb[1][g][i2], fb[1][g][i2 + 1]);
                mma16816(acc[mt][nt], fa[1][mt], fb[0][g][i2], fb[0][g][i2 + 1]);
            }
    }

    // ---- Epilogue ----
    const int which = n0 / Cc;                  // 0=Q,1=K,2=V (256 | 768)
    const int nloc0 = n0 - which * Cc;
    const float scale = (which == 0) ? 0.125f : 1.0f;
    __nv_bfloat16* dh = (which == 0) ? g_qh : (which == 1) ? g_kh : g_vh;
    __nv_bfloat16* dl = (which == 0) ? g_ql : (which == 1) ? g_kl : g_vl;

    const int mrow = m0 + wm * 64 + (l >> 2);
    const int b_   = mrow >> 11;
#pragma unroll
    for (int mt = 0; mt < 4; mt++) {
        const int t1 = (mrow + mt * 16) & (Tt - 1);
#pragma unroll
        for (int nt = 0; nt < 8; nt++) {
            const int n  = nloc0 + wn * 64 + nt * 8 + 2 * (l & 3);
            const int hh = n >> 6;
            const int d  = n & 63;
            const float b0 = bias[which * Cc + n];
            const float b1 = bias[which * Cc + n + 1];
            uint32_t h01, l01, h23, l23;
            split_pack((acc[mt][nt][0] + b0) * scale, (acc[mt][nt][1] + b1) * scale, h01, l01);
            split_pack((acc[mt][nt][2] + b0) * scale, (acc[mt][nt][3] + b1) * scale, h23, l23);
            const size_t i1 = (((size_t)b_ * Hh + hh) * Tt + t1) * DH + d;
            const size_t i2 = i1 + (size_t)8 * DH;
            *(uint32_t*)&dh[i1] = h01;  *(uint32_t*)&dl[i1] = l01;
            *(uint32_t*)&dh[i2] = h23;  *(uint32_t*)&dl[i2] = l23;
        }
    }
}

// ---------------------------------------------------------------------------
// Kernel 2: causal ReLU attention via mma.sync bf16x3.
// Block = (qt,h,b), 128 thr. BQ=64, BK=32, D=64.
// 3-stage cp.async ring (prefetch depth 2); Q staging overlays stage 2.
// ---------------------------------------------------------------------------
__global__ __launch_bounds__(128) void attn_mma(float* __restrict__ out)
{
    __shared__ __align__(128) uint8_t sm[49152];
    // stage s at s*16384: K_hi +0, K_lo +4096, V_hi +8192, V_lo +12288
    // Q staging at 32768 (hi) / 40960 (lo) — overlays stage 2

    const int tid = threadIdx.x;
    const int l   = tid & 31;
    const int w   = tid >> 5;
    const int qt  = (gridDim.x - 1) - blockIdx.x;
    const int h   = blockIdx.y;
    const int b   = blockIdx.z;

    const size_t hb = ((size_t)b * Hh + h) * (size_t)Tt * DH;
    const uint32_t uS = smem_u32(sm);
    const uint32_t uQ = uS + 32768;

#define ATT_ISSUE(j2, st) do {                                              \
    const uint32_t _sb = uS + (st) * 16384;                                 \
    _Pragma("unroll")                                                       \
    for (int _i = 0; _i < 2; _i++) {                                        \
        const int _c = tid + _i * 128;                                      \
        const int _row = _c >> 3;                                           \
        const int _c16 = _c & 7;                                            \
        const uint32_t _so = SWZ(_row, _row * 128 + _c16 * 16);             \
        const size_t _g = hb + (size_t)((j2) * 32 + _row) * DH + _c16 * 8;  \
        CP16(_sb + _so,         g_kh + _g);                                 \
        CP16(_sb + 4096 + _so,  g_kl + _g);                                 \
        CP16(_sb + 8192 + _so,  g_vh + _g);                                 \
        CP16(_sb + 12288 + _so, g_vl + _g);                                 \
    }                                                                       \
    CP_COMMIT();                                                            \
} while (0)

    // Q tile -> staging smem (LDG); first two K/V tiles via cp.async.
#pragma unroll
    for (int i = 0; i < 4; i++) {
        const int c   = tid + i * 128;
        const int row = c >> 3;
        const int c16 = c & 7;
        const size_t g = hb + (size_t)(qt * 64 + row) * DH + c16 * 8;
        const int so = SWZ(row, row * 128 + c16 * 16);
        *(uint4*)(sm + 32768 + so) = *(const uint4*)&g_qh[g];
        *(uint4*)(sm + 40960 + so) = *(const uint4*)&g_ql[g];
    }
    const int ntile = 2 * (qt + 1);
    ATT_ISSUE(0, 0);
    ATT_ISSUE(1, 1);                  // ntile >= 2 always
    __syncthreads();                  // Q visible

    // Q fragments (persist in regs; staging smem is recycled as stage 2)
    uint32_t fq[2][4][4];
    {
        const int row = w * 16 + (l & 15);
#pragma unroll
        for (int s = 0; s < 2; s++)
#pragma unroll
            for (int ks = 0; ks < 4; ks++) {
                const int cb = (ks * 16 + (l >> 4) * 8) * 2;
                ldsm4(fq[s][ks], uQ + s * 8192 + SWZ(row, row * 128 + cb));
            }
    }

    float o[8][4];
#pragma unroll
    for (int i = 0; i < 8; i++)
#pragma unroll
        for (int r = 0; r < 4; r++) o[i][r] = 0.f;

    const int rowg = qt * 64 + w * 16 + (l >> 2);
    int st = 0, pst = 2;

    for (int j2 = 0; j2 < ntile; j2++) {
        if (j2 == ntile - 1) CP_WAIT0(); else CP_WAIT1();
        __syncthreads();
        if (j2 + 2 < ntile) ATT_ISSUE(j2 + 2, pst);

        const uint32_t sb = uS + st * 16384;

        // ---- S = Q . K^T (64 q x 32 k) ----
        float s[4][4];
#pragma unroll
        for (int i = 0; i < 4; i++)
#pragma unroll
            for (int r = 0; r < 4; r++) s[i][r] = 0.f;

#pragma unroll
        for (int ks = 0; ks < 4; ks++) {
            uint32_t fk[2][2][4];
            const int nrow = (l & 7) + 8 * (l >> 4);
            const int cb   = (ks * 16 + 8 * ((l >> 3) & 1)) * 2;
#pragma unroll
            for (int sp = 0; sp < 2; sp++)
#pragma unroll
                for (int g = 0; g < 2; g++) {
                    const int rr = g * 16 + nrow;
                    ldsm4(fk[sp][g], sb + sp * 4096 + SWZ(rr, rr * 128 + cb));
                }
#pragma unroll
            for (int nt = 0; nt < 4; nt++) {
                const int g = nt >> 1, i2 = (nt & 1) * 2;
                mma16816(s[nt], fq[0][ks], fk[0][g][i2], fk[0][g][i2 + 1]);
                mma16816(s[nt], fq[0][ks], fk[1][g][i2], fk[1][g][i2 + 1]);
                mma16816(s[nt], fq[1][ks], fk[0][g][i2], fk[0][g][i2 + 1]);
            }
        }

        // ---- ReLU + causal mask + split into P fragments ----
        uint32_t ph[2][4], pl[2][4];
        const bool needmask = (j2 >= 2 * qt);
#pragma unroll
        for (int nt = 0; nt < 4; nt++) {
            const int colg = j2 * 32 + nt * 8 + 2 * (l & 3);
            float v0 = fmaxf(s[nt][0], 0.f);
            float v1 = fmaxf(s[nt][1], 0.f);
            float v2 = fmaxf(s[nt][2], 0.f);
            float v3 = fmaxf(s[nt][3], 0.f);
            if (needmask) {
                if (colg     > rowg)     v0 = 0.f;
                if (colg + 1 > rowg)     v1 = 0.f;
                if (colg     > rowg + 8) v2 = 0.f;
                if (colg + 1 > rowg + 8) v3 = 0.f;
            }
            const int js = nt >> 1, pos = (nt & 1) * 2;
            split_pack(v0, v1, ph[js][pos],     pl[js][pos]);
            split_pack(v2, v3, ph[js][pos + 1], pl[js][pos + 1]);
        }

        // ---- O += P . V (64 q x 64 d, k=32) ----
#pragma unroll
        for (int js = 0; js < 2; js++) {
            uint32_t fv[2][4][4];
            const int vrow = js * 16 + (l & 15);
#pragma unroll
            for (int sp = 0; sp < 2; sp++)
#pragma unroll
                for (int g = 0; g < 4; g++) {
                    const int cb = (g * 16 + (l >> 4) * 8) * 2;
                    ldsm4t(fv[sp][g], sb + 8192 + sp * 4096 + SWZ(vrow, vrow * 128 + cb));
                }
#pragma unroll
            for (int dt = 0; dt < 8; dt++) {
                const int g = dt >> 1, i2 = (dt & 1) * 2;
                mma16816(o[dt], ph[js], fv[0][g][i2], fv[0][g][i2 + 1]);
                mma16816(o[dt], ph[js], fv[1][g][i2], fv[1][g][i2 + 1]);
                mma16816(o[dt], pl[js], fv[0][g][i2], fv[0][g][i2 + 1]);
            }
        }

        st  = (st  == 2) ? 0 : st + 1;
        pst = (pst == 2) ? 0 : pst + 1;
    }

    // ---- store O ----
    const int r1 = qt * 64 + w * 16 + (l >> 2);
#pragma unroll
    for (int dt = 0; dt < 8; dt++) {
        const int col = h * DH + dt * 8 + 2 * (l & 3);
        *(float2*)&out[((size_t)b * Tt + r1) * Cc + col]     = make_float2(o[dt][0], o[dt][1]);
        *(float2*)&out[((size_t)b * Tt + r1 + 8) * Cc + col] = make_float2(o[dt][2], o[dt][3]);
    }
}

// ---------------------------------------------------------------------------
extern "C" void kernel_launch(void* const* d_in, const int* in_sizes, int n_in,
                              void* d_out, int out_size)
{
    const float* x    = (const float*)d_in[0];
    const float* W    = (const float*)d_in[1];
    const float* bias = (const float*)d_in[2];
    float* out        = (float*)d_out;
    (void)in_sizes; (void)n_in; (void)out_size;

    cvt_x<<<dim3(Mm / 64, Cc / 64), 256>>>(x);
    cvt_w<<<(Cc * N3) / 1024, 256>>>(W);

    dim3 g1(N3 / 256, Mm / 128);    // (9, 64)
    qkv_mma<<<g1, 256>>>(bias);

    dim3 g2(Tt / 64, Hh, Bb);       // (32, 12, 4)
    attn_mma<<<g2, 128>>>(out);
}

// round 7
// speedup vs baseline: 3.7518x; 1.0095x over previous
#include <cuda_runtime.h>
#include <cuda_bf16.h>
#include <cstdint>

// Problem constants (fixed by setup_inputs)
#define Bb 4
#define Tt 2048
#define Cc 768
#define Hh 12
#define DH 64
#define Mm (Bb * Tt)      // 8192
#define N3 (3 * Cc)       // 2304
#define NKSTEP (Cc / 16)  // 48

// ---------------------------------------------------------------------------
// Device scratch: bf16 hi/lo splits.
// x splits are stored TRANSPOSED: [K][M]. W splits natural [K][N].
// q/k/v: [B,H,T,D].
// ---------------------------------------------------------------------------
__device__ __nv_bfloat16 g_xh[(size_t)Cc * Mm], g_xl[(size_t)Cc * Mm];
__device__ __nv_bfloat16 g_wh[(size_t)Cc * N3], g_wl[(size_t)Cc * N3];
__device__ __nv_bfloat16 g_qh[(size_t)Bb * Hh * Tt * DH], g_ql[(size_t)Bb * Hh * Tt * DH];
__device__ __nv_bfloat16 g_kh[(size_t)Bb * Hh * Tt * DH], g_kl[(size_t)Bb * Hh * Tt * DH];
__device__ __nv_bfloat16 g_vh[(size_t)Bb * Hh * Tt * DH], g_vl[(size_t)Bb * Hh * Tt * DH];

// ---------------------------------------------------------------------------
// Helpers
// ---------------------------------------------------------------------------
__device__ __forceinline__ uint32_t smem_u32(const void* p) {
    uint32_t a;
    asm("{ .reg .u64 t; cvta.to.shared.u64 t, %1; cvt.u32.u64 %0, t; }"
        : "=r"(a) : "l"(p));
    return a;
}
__device__ __forceinline__ void ldsm4(uint32_t r[4], uint32_t a) {
    asm volatile("ldmatrix.sync.aligned.m8n8.x4.shared.b16 {%0,%1,%2,%3}, [%4];"
                 : "=r"(r[0]), "=r"(r[1]), "=r"(r[2]), "=r"(r[3]) : "r"(a));
}
__device__ __forceinline__ void ldsm4t(uint32_t r[4], uint32_t a) {
    asm volatile("ldmatrix.sync.aligned.m8n8.x4.trans.shared.b16 {%0,%1,%2,%3}, [%4];"
                 : "=r"(r[0]), "=r"(r[1]), "=r"(r[2]), "=r"(r[3]) : "r"(a));
}
__device__ __forceinline__ void mma16816(float* c, const uint32_t* a, uint32_t b0, uint32_t b1) {
    asm volatile(
        "mma.sync.aligned.m16n8k16.row.col.f32.bf16.bf16.f32 "
        "{%0,%1,%2,%3}, {%4,%5,%6,%7}, {%8,%9}, {%0,%1,%2,%3};"
        : "+f"(c[0]), "+f"(c[1]), "+f"(c[2]), "+f"(c[3])
        : "r"(a[0]), "r"(a[1]), "r"(a[2]), "r"(a[3]), "r"(b0), "r"(b1));
}
__device__ __forceinline__ void split_pack(float x0, float x1, uint32_t& hi, uint32_t& lo) {
    __nv_bfloat16 h0 = __float2bfloat16_rn(x0), h1 = __float2bfloat16_rn(x1);
    hi = ((uint32_t)*(uint16_t*)&h1 << 16) | *(uint16_t*)&h0;
    __nv_bfloat16 l0 = __float2bfloat16_rn(x0 - __bfloat162float(h0));
    __nv_bfloat16 l1 = __float2bfloat16_rn(x1 - __bfloat162float(h1));
    lo = ((uint32_t)*(uint16_t*)&l1 << 16) | *(uint16_t*)&l0;
}

#define CP16(s, g) \
    asm volatile("cp.async.cg.shared.global [%0], [%1], 16;" :: "r"(s), "l"(g))
#define CP_COMMIT() asm volatile("cp.async.commit_group;" ::: "memory")
#define CP_WAIT0()  asm volatile("cp.async.wait_group 0;" ::: "memory")
#define CP_WAIT1()  asm volatile("cp.async.wait_group 1;" ::: "memory")

// swizzle: XOR row low bits into 16B-chunk index (row-size-agnostic, 128B period)
#define SWZ(row, byteoff) ((byteoff) ^ (((row) & 7) << 4))

// ---------------------------------------------------------------------------
// cvt_x: fp32 x[M][K] -> bf16 hi/lo TRANSPOSED [K][M]
// ---------------------------------------------------------------------------
__global__ __launch_bounds__(256) void cvt_x(const float* __restrict__ x) {
    __shared__ float S[64][65];
    const int m0 = blockIdx.x * 64, k0 = blockIdx.y * 64;
    const int tid = threadIdx.x;
#pragma unroll
    for (int i = 0; i < 4; i++) {
        const int c = tid + i * 256;         // 0..1023
        const int row = c >> 4;              // m 0..63
        const int c4 = (c & 15) * 4;         // k
        float4 v = *(const float4*)&x[(size_t)(m0 + row) * Cc + k0 + c4];
        S[row][c4] = v.x; S[row][c4 + 1] = v.y; S[row][c4 + 2] = v.z; S[row][c4 + 3] = v.w;
    }
    __syncthreads();
#pragma unroll
    for (int i = 0; i < 2; i++) {
        const int c = tid + i * 256;         // 0..511
        const int k = c >> 3;                // 0..63
        const int mc = c & 7;                // m-chunk of 8
        uint32_t hw[4], lw[4];
#pragma unroll
        for (int e = 0; e < 4; e++)
            split_pack(S[mc * 8 + 2 * e][k], S[mc * 8 + 2 * e + 1][k], hw[e], lw[e]);
        const size_t g = (size_t)(k0 + k) * Mm + m0 + mc * 8;
        *(uint4*)&g_xh[g] = make_uint4(hw[0], hw[1], hw[2], hw[3]);
        *(uint4*)&g_xl[g] = make_uint4(lw[0], lw[1], lw[2], lw[3]);
    }
}
__global__ __launch_bounds__(256) void cvt_w(const float* __restrict__ W) {
    const size_t base = ((size_t)blockIdx.x * 256 + threadIdx.x) * 4;
    float4 v = *(const float4*)&W[base];
    uint32_t h01, l01, h23, l23;
    split_pack(v.x, v.y, h01, l01);
    split_pack(v.z, v.w, h23, l23);
    *(uint2*)&g_wh[base] = make_uint2(h01, h23);
    *(uint2*)&g_wl[base] = make_uint2(l01, l23);
}

// ---------------------------------------------------------------------------
// Kernel 1: qkv = x @ W + b via mma.sync bf16x3.
// 128(m) x 128(n) block tile, BK=16, 128 thr, 4 warps (2m x 2n), warp 64x64.
// Stage (16KB): A^T hi +0, A^T lo +4096, B hi +8192, B lo +12288.
// 3 stages = 48KB, prefetch depth 2. 2 blocks/SM.
// ---------------------------------------------------------------------------
__global__ __launch_bounds__(128) void qkv_mma(const float* __restrict__ bias) {
    __shared__ __align__(128) uint8_t sm[49152];

    const int tid = threadIdx.x;
    const int l   = tid & 31;
    const int w   = tid >> 5;
    const int wm  = w >> 1;          // 0..1 (64 m each)
    const int wn  = w & 1;           // 0..1 (64 n each)
    const int m0  = blockIdx.y * 128;
    const int n0  = blockIdx.x * 128;

    const uint32_t uS = smem_u32(sm);

    float acc[4][8][4];
#pragma unroll
    for (int i = 0; i < 4; i++)
#pragma unroll
        for (int j = 0; j < 8; j++)
#pragma unroll
            for (int r = 0; r < 4; r++) acc[i][j][r] = 0.f;

    // cp.async coords: A and B tiles are both 16 rows x 256B.
    const int cr = tid >> 3;                 // row 0..15
    const int cc = (tid & 7) * 2;            // 16B-chunk 0..14 (2 per thread)
    const uint32_t so0 = (uint32_t)SWZ(cr, cr * 256 + cc * 16);
    const uint32_t so1 = (uint32_t)SWZ(cr, cr * 256 + cc * 16 + 16);

#define QKV_ISSUE(kb, st) do {                                                \
    const int _k = (kb) * 16 + cr;                                            \
    const uint32_t _b = uS + (st) * 16384;                                    \
    const size_t _ga = (size_t)_k * Mm + m0 + cc * 8;                         \
    const size_t _gb = (size_t)_k * N3 + n0 + cc * 8;                         \
    CP16(_b + so0,         g_xh + _ga);                                       \
    CP16(_b + so1,         g_xh + _ga + 8);                                   \
    CP16(_b + 4096 + so0,  g_xl + _ga);                                       \
    CP16(_b + 4096 + so1,  g_xl + _ga + 8);                                   \
    CP16(_b + 8192 + so0,  g_wh + _gb);                                       \
    CP16(_b + 8192 + so1,  g_wh + _gb + 8);                                   \
    CP16(_b + 12288 + so0, g_wl + _gb);                                       \
    CP16(_b + 12288 + so1, g_wl + _gb + 8);                                   \
    CP_COMMIT();                                                              \
} while (0)

    // ldsm coords (16x256B k-major tiles, trans loads)
    const int arow = (l & 7) + 8 * (l >> 4);
    const int abyt = wm * 128 + ((l >> 3) & 1) * 16;
    const int brow = (l & 15);
    const int bbyt = wn * 128 + (l >> 4) * 16;

    QKV_ISSUE(0, 0);
    QKV_ISSUE(1, 1);

    int st = 0;
    for (int kb = 0; kb < NKSTEP; kb++) {
        if (kb == NKSTEP - 1) CP_WAIT0(); else CP_WAIT1();
        __syncthreads();
        if (kb + 2 < NKSTEP) QKV_ISSUE(kb + 2, (st + 2 > 2) ? st - 1 : st + 2);

        const uint32_t sb = uS + st * 16384;
        uint32_t fa[2][4][4], fb[2][4][4];
#pragma unroll
        for (int sp = 0; sp < 2; sp++) {
#pragma unroll
            for (int mt = 0; mt < 4; mt++)
                ldsm4t(fa[sp][mt], sb + sp * 4096 + SWZ(arow, arow * 256 + abyt + mt * 32));
#pragma unroll
            for (int g = 0; g < 4; g++)
                ldsm4t(fb[sp][g], sb + 8192 + sp * 4096 + SWZ(brow, brow * 256 + bbyt + g * 32));
        }

#pragma unroll
        for (int mt = 0; mt < 4; mt++)
#pragma unroll
            for (int nt = 0; nt < 8; nt++) {
                const int g = nt >> 1, i2 = (nt & 1) * 2;
                mma16816(acc[mt][nt], fa[0][mt], fb[0][g][i2], fb[0][g][i2 + 1]);
                mma16816(acc[mt][nt], fa[0][mt], fb[1][g][i2], fb[1][g][i2 + 1]);
                mma16816(acc[mt][nt], fa[1][mt], fb[0][g][i2], fb[0][g][i2 + 1]);
            }

        st = (st == 2) ? 0 : st + 1;
    }

    // ---- Epilogue ----
    const int which = n0 / Cc;                  // 0=Q,1=K,2=V (128 | 768)
    const int nloc0 = n0 - which * Cc;
    const float scale = (which == 0) ? 0.125f : 1.0f;
    __nv_bfloat16* dh = (which == 0) ? g_qh : (which == 1) ? g_kh : g_vh;
    __nv_bfloat16* dl = (which == 0) ? g_ql : (which == 1) ? g_kl : g_vl;

    const int mrow = m0 + wm * 64 + (l >> 2);
    const int b_   = mrow >> 11;
#pragma unroll
    for (int mt = 0; mt < 4; mt++) {
        const int t1 = (mrow + mt * 16) & (Tt - 1);
#pragma unroll
        for (int nt = 0; nt < 8; nt++) {
            const int n  = nloc0 + wn * 64 + nt * 8 + 2 * (l & 3);
            const int hh = n >> 6;
            const int d  = n & 63;
            const float b0 = bias[which * Cc + n];
            const float b1 = bias[which * Cc + n + 1];
            uint32_t h01, l01, h23, l23;
            split_pack((acc[mt][nt][0] + b0) * scale, (acc[mt][nt][1] + b1) * scale, h01, l01);
            split_pack((acc[mt][nt][2] + b0) * scale, (acc[mt][nt][3] + b1) * scale, h23, l23);
            const size_t i1 = (((size_t)b_ * Hh + hh) * Tt + t1) * DH + d;
            const size_t i2 = i1 + (size_t)8 * DH;
            *(uint32_t*)&dh[i1] = h01;  *(uint32_t*)&dl[i1] = l01;
            *(uint32_t*)&dh[i2] = h23;  *(uint32_t*)&dl[i2] = l23;
        }
    }
}

// ---------------------------------------------------------------------------
// Kernel 2: causal ReLU attention via mma.sync bf16x3 (unchanged from R6).
// Block = (qt,h,b), 128 thr. BQ=64, BK=32, D=64.
// 3-stage cp.async ring; Q staging overlays stage 2.
// ---------------------------------------------------------------------------
__global__ __launch_bounds__(128) void attn_mma(float* __restrict__ out)
{
    __shared__ __align__(128) uint8_t sm[49152];

    const int tid = threadIdx.x;
    const int l   = tid & 31;
    const int w   = tid >> 5;
    const int qt  = (gridDim.x - 1) - blockIdx.x;
    const int h   = blockIdx.y;
    const int b   = blockIdx.z;

    const size_t hb = ((size_t)b * Hh + h) * (size_t)Tt * DH;
    const uint32_t uS = smem_u32(sm);
    const uint32_t uQ = uS + 32768;

#define ATT_ISSUE(j2, st) do {                                              \
    const uint32_t _sb = uS + (st) * 16384;                                 \
    _Pragma("unroll")                                                       \
    for (int _i = 0; _i < 2; _i++) {                                        \
        const int _c = tid + _i * 128;                                      \
        const int _row = _c >> 3;                                           \
        const int _c16 = _c & 7;                                            \
        const uint32_t _so = SWZ(_row, _row * 128 + _c16 * 16);             \
        const size_t _g = hb + (size_t)((j2) * 32 + _row) * DH + _c16 * 8;  \
        CP16(_sb + _so,         g_kh + _g);                                 \
        CP16(_sb + 4096 + _so,  g_kl + _g);                                 \
        CP16(_sb + 8192 + _so,  g_vh + _g);                                 \
        CP16(_sb + 12288 + _so, g_vl + _g);                                 \
    }                                                                       \
    CP_COMMIT();                                                            \
} while (0)

    // Q tile -> staging smem (LDG); first two K/V tiles via cp.async.
#pragma unroll
    for (int i = 0; i < 4; i++) {
        const int c   = tid + i * 128;
        const int row = c >> 3;
        const int c16 = c & 7;
        const size_t g = hb + (size_t)(qt * 64 + row) * DH + c16 * 8;
        const int so = SWZ(row, row * 128 + c16 * 16);
        *(uint4*)(sm + 32768 + so) = *(const uint4*)&g_qh[g];
        *(uint4*)(sm + 40960 + so) = *(const uint4*)&g_ql[g];
    }
    const int ntile = 2 * (qt + 1);
    ATT_ISSUE(0, 0);
    ATT_ISSUE(1, 1);
    __syncthreads();

    // Q fragments (persist in regs; staging smem is recycled as stage 2)
    uint32_t fq[2][4][4];
    {
        const int row = w * 16 + (l & 15);
#pragma unroll
        for (int s = 0; s < 2; s++)
#pragma unroll
            for (int ks = 0; ks < 4; ks++) {
                const int cb = (ks * 16 + (l >> 4) * 8) * 2;
                ldsm4(fq[s][ks], uQ + s * 8192 + SWZ(row, row * 128 + cb));
            }
    }

    float o[8][4];
#pragma unroll
    for (int i = 0; i < 8; i++)
#pragma unroll
        for (int r = 0; r < 4; r++) o[i][r] = 0.f;

    const int rowg = qt * 64 + w * 16 + (l >> 2);
    int st = 0, pst = 2;

    for (int j2 = 0; j2 < ntile; j2++) {
        if (j2 == ntile - 1) CP_WAIT0(); else CP_WAIT1();
        __syncthreads();
        if (j2 + 2 < ntile) ATT_ISSUE(j2 + 2, pst);

        const uint32_t sb = uS + st * 16384;

        // ---- S = Q . K^T (64 q x 32 k) ----
        float s[4][4];
#pragma unroll
        for (int i = 0; i < 4; i++)
#pragma unroll
            for (int r = 0; r < 4; r++) s[i][r] = 0.f;

#pragma unroll
        for (int ks = 0; ks < 4; ks++) {
            uint32_t fk[2][2][4];
            const int nrow = (l & 7) + 8 * (l >> 4);
            const int cb   = (ks * 16 + 8 * ((l >> 3) & 1)) * 2;
#pragma unroll
            for (int sp = 0; sp < 2; sp++)
#pragma unroll
                for (int g = 0; g < 2; g++) {
                    const int rr = g * 16 + nrow;
                    ldsm4(fk[sp][g], sb + sp * 4096 + SWZ(rr, rr * 128 + cb));
                }
#pragma unroll
            for (int nt = 0; nt < 4; nt++) {
                const int g = nt >> 1, i2 = (nt & 1) * 2;
                mma16816(s[nt], fq[0][ks], fk[0][g][i2], fk[0][g][i2 + 1]);
                mma16816(s[nt], fq[0][ks], fk[1][g][i2], fk[1][g][i2 + 1]);
                mma16816(s[nt], fq[1][ks], fk[0][g][i2], fk[0][g][i2 + 1]);
            }
        }

        // ---- ReLU + causal mask + split into P fragments ----
        uint32_t ph[2][4], pl[2][4];
        const bool needmask = (j2 >= 2 * qt);
#pragma unroll
        for (int nt = 0; nt < 4; nt++) {
            const int colg = j2 * 32 + nt * 8 + 2 * (l & 3);
            float v0 = fmaxf(s[nt][0], 0.f);
            float v1 = fmaxf(s[nt][1], 0.f);
            float v2 = fmaxf(s[nt][2], 0.f);
            float v3 = fmaxf(s[nt][3], 0.f);
            if (needmask) {
                if (colg     > rowg)     v0 = 0.f;
                if (colg + 1 > rowg)     v1 = 0.f;
                if (colg     > rowg + 8) v2 = 0.f;
                if (colg + 1 > rowg + 8) v3 = 0.f;
            }
            const int js = nt >> 1, pos = (nt & 1) * 2;
            split_pack(v0, v1, ph[js][pos],     pl[js][pos]);
            split_pack(v2, v3, ph[js][pos + 1], pl[js][pos + 1]);
        }

        // ---- O += P . V (64 q x 64 d, k=32) ----
#pragma unroll
        for (int js = 0; js < 2; js++) {
            uint32_t fv[2][4][4];
            const int vrow = js * 16 + (l & 15);
#pragma unroll
            for (int sp = 0; sp < 2; sp++)
#pragma unroll
                for (int g = 0; g < 4; g++) {
                    const int cb = (g * 16 + (l >> 4) * 8) * 2;
                    ldsm4t(fv[sp][g], sb + 8192 + sp * 4096 + SWZ(vrow, vrow * 128 + cb));
                }
#pragma unroll
            for (int dt = 0; dt < 8; dt++) {
                const int g = dt >> 1, i2 = (dt & 1) * 2;
                mma16816(o[dt], ph[js], fv[0][g][i2], fv[0][g][i2 + 1]);
                mma16816(o[dt], ph[js], fv[1][g][i2], fv[1][g][i2 + 1]);
                mma16816(o[dt], pl[js], fv[0][g][i2], fv[0][g][i2 + 1]);
            }
        }

        st  = (st  == 2) ? 0 : st + 1;
        pst = (pst == 2) ? 0 : pst + 1;
    }

    // ---- store O ----
    const int r1 = qt * 64 + w * 16 + (l >> 2);
#pragma unroll
    for (int dt = 0; dt < 8; dt++) {
        const int col = h * DH + dt * 8 + 2 * (l & 3);
        *(float2*)&out[((size_t)b * Tt + r1) * Cc + col]     = make_float2(o[dt][0], o[dt][1]);
        *(float2*)&out[((size_t)b * Tt + r1 + 8) * Cc + col] = make_float2(o[dt][2], o[dt][3]);
    }
}

// ---------------------------------------------------------------------------
extern "C" void kernel_launch(void* const* d_in, const int* in_sizes, int n_in,
                              void* d_out, int out_size)
{
    const float* x    = (const float*)d_in[0];
    const float* W    = (const float*)d_in[1];
    const float* bias = (const float*)d_in[2];
    float* out        = (float*)d_out;
    (void)in_sizes; (void)n_in; (void)out_size;

    cvt_x<<<dim3(Mm / 64, Cc / 64), 256>>>(x);
    cvt_w<<<(Cc * N3) / 1024, 256>>>(W);

    dim3 g1(N3 / 128, Mm / 128);    // (18, 64)
    qkv_mma<<<g1, 128>>>(bias);

    dim3 g2(Tt / 64, Hh, Bb);       // (32, 12, 4)
    attn_mma<<<g2, 128>>>(out);
}